// round 7
// baseline (speedup 1.0000x reference)
#include <cuda_runtime.h>
#include <cuda_fp16.h>
#include <math.h>

#define MAXN 100000
#define MAXE 1600000
#define H 64
#define H2 128
#define PAD 64   // max degree bucket (Poisson(16): P(deg>=64) ~ 1e-20)
#define LOG2E 1.44269504088896f

typedef unsigned long long ull;

// ---------------- scratch (static device globals; no allocs) ----------------
__device__ float d_bufA[MAXN * H];       // agg output (both layers)
__device__ float d_bufB[MAXN * H];       // h1
__device__ float d_bufC[MAXN * H];       // relu(LN(h1))
__device__ float d_bufE[MAXN * H];       // h0
__device__ uint4 d_P[MAXN * 16];         // per-node (vw,w) half2 pairs: 256B/node
__device__ int   d_cnt[MAXN];
__device__ int   d_adj[MAXN * PAD];

// packed fp32x2 helpers (sm_103a FFMA2 path)
#define PK(d, lo, hi)  asm("mov.b64 %0, {%1, %2};" : "=l"(d) : "f"(lo), "f"(hi))
#define UPK(lo, hi, s) asm("mov.b64 {%0, %1}, %2;" : "=f"(lo), "=f"(hi) : "l"(s))
#define FMA2(d, a, b, c) asm("fma.rn.f32x2 %0, %1, %2, %3;" : "=l"(d) : "l"(a), "l"(b), "l"(c))

// ---------------- encoder: h = x @ W_enc + b_enc; fused P(t1); zero cnt -----
__global__ void k_encoder(const float* __restrict__ x, const float* __restrict__ W,
                          const float* __restrict__ b, float* __restrict__ h,
                          uint4* __restrict__ P, const float* __restrict__ tptr,
                          int* __restrict__ cnt, int N) {
    __shared__ float4 sW[16 * 16];   // [k][q]
    __shared__ float4 sB[16];
    int tid = threadIdx.x;
    if (tid < 256) sW[tid] = ((const float4*)W)[tid];
    if (tid < 16)  sB[tid] = ((const float4*)b)[tid];
    __syncthreads();
    int idx = blockIdx.x * blockDim.x + threadIdx.x;   // one per (node, q)
    if (idx < N) cnt[idx] = 0;
    int total = N * 16;
    if (idx >= total) return;
    int n = idx >> 4, q = idx & 15;
    const float4* xr = (const float4*)(x + n * 16);
    float4 x0 = xr[0], x1 = xr[1], x2 = xr[2], x3 = xr[3];
    float4 acc = sB[q];
    #define ESTEP(xv, kk) { float4 w = sW[(kk) * 16 + q]; \
        acc.x += (xv) * w.x; acc.y += (xv) * w.y; acc.z += (xv) * w.z; acc.w += (xv) * w.w; }
    ESTEP(x0.x, 0)  ESTEP(x0.y, 1)  ESTEP(x0.z, 2)  ESTEP(x0.w, 3)
    ESTEP(x1.x, 4)  ESTEP(x1.y, 5)  ESTEP(x1.z, 6)  ESTEP(x1.w, 7)
    ESTEP(x2.x, 8)  ESTEP(x2.y, 9)  ESTEP(x2.z, 10) ESTEP(x2.w, 11)
    ESTEP(x3.x, 12) ESTEP(x3.y, 13) ESTEP(x3.z, 14) ESTEP(x3.w, 15)
    #undef ESTEP
    ((float4*)h)[idx] = acc;
    // fused layer-1 P precompute: v = relu(h0)+eps, w = exp2(v*t*log2e)
    float c = __ldg(tptr) * LOG2E;
    float vx = fmaxf(acc.x, 0.f) + 1e-7f;
    float vy = fmaxf(acc.y, 0.f) + 1e-7f;
    float vz = fmaxf(acc.z, 0.f) + 1e-7f;
    float vw = fmaxf(acc.w, 0.f) + 1e-7f;
    float wx = exp2f(vx * c), wy = exp2f(vy * c);
    float wz = exp2f(vz * c), ww = exp2f(vw * c);
    __half2 h0 = __floats2half2_rn(vx * wx, wx);
    __half2 h1 = __floats2half2_rn(vy * wy, wy);
    __half2 h2 = __floats2half2_rn(vz * wz, wz);
    __half2 h3 = __floats2half2_rn(vw * ww, ww);
    uint4 u;
    u.x = *(unsigned*)&h0; u.y = *(unsigned*)&h1;
    u.z = *(unsigned*)&h2; u.w = *(unsigned*)&h3;
    P[idx] = u;
}

// ---------------- bucket placement (single-kernel CSR) ----------------------
__global__ void k_place(const int* __restrict__ src, const int* __restrict__ dst,
                        int* __restrict__ cnt, int* __restrict__ adj, int E) {
    int e = blockIdx.x * blockDim.x + threadIdx.x;
    if (e >= E) return;
    int d = dst[e];
    int p = atomicAdd(&cnt[d], 1);
    if (p < PAD) adj[(d << 6) + p] = src[e];
}

// ---------------- GENConv softmax aggregation: fp16 P gather ----------------
// 32 threads per node (1 warp): 2 subgroups of 16 take alternating int4 chunks.
// out[n] = (sum vw[s]) / (sum w[s] + 1e-16) + feat[n]; fp32 accumulation.
#define ACCP(p) { \
    float2 q0 = __half22float2(*(__half2*)&(p).x); \
    float2 q1 = __half22float2(*(__half2*)&(p).y); \
    float2 q2 = __half22float2(*(__half2*)&(p).z); \
    float2 q3 = __half22float2(*(__half2*)&(p).w); \
    n0 += q0.x; d0 += q0.y; n1 += q1.x; d1 += q1.y; \
    n2 += q2.x; d2 += q2.y; n3 += q3.x; d3 += q3.y; }

__global__ void __launch_bounds__(256)
k_agg(const float4* __restrict__ feat4, float4* __restrict__ out4,
      const uint4* __restrict__ P, const int* __restrict__ cnt,
      const int* __restrict__ adj, int N) {
    int gid = (blockIdx.x * 256 + threadIdx.x) >> 5;
    if (gid >= N) return;
    int lane = threadIdx.x & 31;
    int sub = lane >> 4;     // 0/1: chunk parity this thread covers
    int f = lane & 15;       // feature quad
    int deg = cnt[gid]; deg = min(deg, PAD);
    const int4* lst4 = (const int4*)(adj + (gid << 6));
    float n0 = 0.f, n1 = 0.f, n2 = 0.f, n3 = 0.f;
    float d0 = 0.f, d1 = 0.f, d2 = 0.f, d3 = 0.f;
    int full = deg >> 2;
    for (int c = sub; c < full; c += 2) {
        int4 s = lst4[c];
        uint4 p0 = P[s.x * 16 + f];
        uint4 p1 = P[s.y * 16 + f];
        uint4 p2 = P[s.z * 16 + f];
        uint4 p3 = P[s.w * 16 + f];
        ACCP(p0); ACCP(p1); ACCP(p2); ACCP(p3);
    }
    int r = deg & 3;
    if (r && ((full & 1) == sub)) {
        int4 s = lst4[full];
        uint4 p0 = P[s.x * 16 + f]; ACCP(p0);
        if (r > 1) { uint4 p1 = P[s.y * 16 + f]; ACCP(p1); }
        if (r > 2) { uint4 p2 = P[s.z * 16 + f]; ACCP(p2); }
    }
    // combine the two subgroups
    n0 += __shfl_xor_sync(0xffffffffu, n0, 16);
    n1 += __shfl_xor_sync(0xffffffffu, n1, 16);
    n2 += __shfl_xor_sync(0xffffffffu, n2, 16);
    n3 += __shfl_xor_sync(0xffffffffu, n3, 16);
    d0 += __shfl_xor_sync(0xffffffffu, d0, 16);
    d1 += __shfl_xor_sync(0xffffffffu, d1, 16);
    d2 += __shfl_xor_sync(0xffffffffu, d2, 16);
    d3 += __shfl_xor_sync(0xffffffffu, d3, 16);
    if (sub == 0) {
        float4 self = feat4[gid * 16 + f];
        float4 o;
        o.x = n0 / (d0 + 1e-16f) + self.x;
        o.y = n1 / (d1 + 1e-16f) + self.y;
        o.z = n2 / (d2 + 1e-16f) + self.z;
        o.w = n3 / (d3 + 1e-16f) + self.w;
        out4[gid * 16 + f] = o;
    }
}

// ---------------- fused MLP: relu(LN(in@W1+b1)) @ W2 + b2 + fused epilogue --
// MODE 0: out=h1, out2=relu(LN64(h1; gx,bx)); ALSO writes P for layer-2 (t=tp)
// MODE 1: h2 = gemm + res; final head -> sigmoid/logits
#define TM 128
#define HSTRIDE 132
template <int MODE>
__global__ void __launch_bounds__(512, 1)
k_mlp(const float* __restrict__ in, float* __restrict__ out, float* __restrict__ out2,
      const float* __restrict__ res,
      const float* __restrict__ W1, const float* __restrict__ b1,
      const float* __restrict__ g1, const float* __restrict__ be1,
      const float* __restrict__ W2, const float* __restrict__ b2,
      const float* __restrict__ gx, const float* __restrict__ bx,
      const float* __restrict__ Wl, const float* __restrict__ bl,
      uint4* __restrict__ Pout, const float* __restrict__ tp, int N) {
    extern __shared__ float sm[];
    float* sW1  = sm;                       // 8192
    float* sW2  = sW1 + 8192;               // 8192
    float* sIn  = sW2 + 8192;               // 8192 (transposed [k][m])
    float* sHid = sIn + 8192;               // 128 x 132
    float* sRs  = sHid + 128 * HSTRIDE;     // 16 x 128
    float* sRq  = sRs + 2048;               // 16 x 128
    float* sMu  = sRq + 2048;               // 128
    float* sInv = sMu + 128;                // 128
    float* sb1  = sInv + 128;               // 128
    float* sg1  = sb1 + 128;                // 128
    float* sbe1 = sg1 + 128;                // 128
    float* sb2  = sbe1 + 128;               // 64
    float* sgx  = sb2 + 64;                 // 64
    float* sbx  = sgx + 64;                 // 64
    float* sWl  = sbx + 64;                 // 64

    const int tid = threadIdx.x;
    const int mg  = tid & 31;    // 32 m-groups x 4 nodes
    const int jg  = tid >> 5;    // 16 j-groups

    // load weights/biases
    {
        const float4* W14 = (const float4*)W1;
        const float4* W24 = (const float4*)W2;
        float4* sW14 = (float4*)sW1;
        float4* sW24 = (float4*)sW2;
        #pragma unroll
        for (int i = 0; i < 4; i++) {
            sW14[tid + i * 512] = W14[tid + i * 512];
            sW24[tid + i * 512] = W24[tid + i * 512];
        }
        if (tid < 128) { sb1[tid] = b1[tid]; sg1[tid] = g1[tid]; sbe1[tid] = be1[tid]; }
        else if (tid < 192) sb2[tid - 128] = b2[tid - 128];
        else if (tid < 256) sgx[tid - 192] = gx[tid - 192];
        else if (tid < 320) sbx[tid - 256] = bx[tid - 256];
        else if (MODE == 1 && tid < 384) sWl[tid - 320] = Wl[tid - 320];
    }

    // load + transpose input tile: sIn[k][m]
    {
        int nl = tid & 127;
        int q  = tid >> 7;       // 0..3
        int n  = blockIdx.x * TM + nl;
        if (n >= N) n = N - 1;
        const float4* ip = (const float4*)(in + n * H);
        #pragma unroll
        for (int i = 0; i < 4; i++) {
            float4 v = ip[q * 4 + i];
            int k0 = (q * 4 + i) * 4;
            sIn[(k0 + 0) * TM + nl] = v.x;
            sIn[(k0 + 1) * TM + nl] = v.y;
            sIn[(k0 + 2) * TM + nl] = v.z;
            sIn[(k0 + 3) * TM + nl] = v.w;
        }
    }
    __syncthreads();

    // ---- GEMM1: [128 x 64] @ [64 x 128]; thread tile 4m x 8j ----
    ull acc[4][4];
    #pragma unroll
    for (int a = 0; a < 4; a++)
        #pragma unroll
        for (int bq = 0; bq < 4; bq++) acc[a][bq] = 0ull;

    const float4* sIn4 = (const float4*)sIn;
    const float4* sW14 = (const float4*)sW1;
    #pragma unroll 8
    for (int k = 0; k < 64; k++) {
        float4 a  = sIn4[k * 32 + mg];
        float4 w0 = sW14[k * 32 + (jg << 1)];
        float4 w1 = sW14[k * 32 + (jg << 1) + 1];
        ull pa0, pa1, pa2, pa3, q0, q1, q2, q3;
        PK(pa0, a.x, a.x); PK(pa1, a.y, a.y); PK(pa2, a.z, a.z); PK(pa3, a.w, a.w);
        PK(q0, w0.x, w0.y); PK(q1, w0.z, w0.w); PK(q2, w1.x, w1.y); PK(q3, w1.z, w1.w);
        FMA2(acc[0][0], pa0, q0, acc[0][0]); FMA2(acc[0][1], pa0, q1, acc[0][1]);
        FMA2(acc[0][2], pa0, q2, acc[0][2]); FMA2(acc[0][3], pa0, q3, acc[0][3]);
        FMA2(acc[1][0], pa1, q0, acc[1][0]); FMA2(acc[1][1], pa1, q1, acc[1][1]);
        FMA2(acc[1][2], pa1, q2, acc[1][2]); FMA2(acc[1][3], pa1, q3, acc[1][3]);
        FMA2(acc[2][0], pa2, q0, acc[2][0]); FMA2(acc[2][1], pa2, q1, acc[2][1]);
        FMA2(acc[2][2], pa2, q2, acc[2][2]); FMA2(acc[2][3], pa2, q3, acc[2][3]);
        FMA2(acc[3][0], pa3, q0, acc[3][0]); FMA2(acc[3][1], pa3, q1, acc[3][1]);
        FMA2(acc[3][2], pa3, q2, acc[3][2]); FMA2(acc[3][3], pa3, q3, acc[3][3]);
    }

    // bias + per-node partial LN sums (over 128 hidden)
    float hreg[4][8];
    {
        float4 psum, psq;
        float* ps = (float*)&psum;
        float* pq = (float*)&psq;
        #pragma unroll
        for (int mi = 0; mi < 4; mi++) {
            float s = 0.f, q = 0.f;
            #pragma unroll
            for (int jp = 0; jp < 4; jp++) {
                float lo, hi;
                UPK(lo, hi, acc[mi][jp]);
                lo += sb1[(jg << 3) + 2 * jp];
                hi += sb1[(jg << 3) + 2 * jp + 1];
                hreg[mi][2 * jp] = lo; hreg[mi][2 * jp + 1] = hi;
                s += lo + hi; q += lo * lo + hi * hi;
            }
            ps[mi] = s; pq[mi] = q;
        }
        *(float4*)&sRs[jg * TM + (mg << 2)] = psum;
        *(float4*)&sRq[jg * TM + (mg << 2)] = psq;
    }
    __syncthreads();
    if (tid < TM) {
        float s = 0.f, q = 0.f;
        #pragma unroll
        for (int g = 0; g < 16; g++) { s += sRs[g * TM + tid]; q += sRq[g * TM + tid]; }
        float mu = s * (1.f / 128.f);
        float var = q * (1.f / 128.f) - mu * mu;
        sMu[tid] = mu;
        sInv[tid] = rsqrtf(var + 1e-5f);
    }
    __syncthreads();

    // LN + ReLU -> sHid[j][m]
    {
        float mu[4], iv[4];
        #pragma unroll
        for (int mi = 0; mi < 4; mi++) { mu[mi] = sMu[(mg << 2) + mi]; iv[mi] = sInv[(mg << 2) + mi]; }
        #pragma unroll
        for (int jj = 0; jj < 8; jj++) {
            int j = (jg << 3) + jj;
            float gg = sg1[j], bb = sbe1[j];
            float4 v;
            v.x = fmaxf((hreg[0][jj] - mu[0]) * iv[0] * gg + bb, 0.f);
            v.y = fmaxf((hreg[1][jj] - mu[1]) * iv[1] * gg + bb, 0.f);
            v.z = fmaxf((hreg[2][jj] - mu[2]) * iv[2] * gg + bb, 0.f);
            v.w = fmaxf((hreg[3][jj] - mu[3]) * iv[3] * gg + bb, 0.f);
            *(float4*)&sHid[j * HSTRIDE + (mg << 2)] = v;
        }
    }
    __syncthreads();

    // ---- GEMM2: [128 x 128] @ [128 x 64]; thread tile 4m x 4j ----
    ull c2[4][2];
    #pragma unroll
    for (int a = 0; a < 4; a++) { c2[a][0] = 0ull; c2[a][1] = 0ull; }

    const float4* sW24 = (const float4*)sW2;
    #pragma unroll 8
    for (int k = 0; k < 128; k++) {
        float4 a = *(const float4*)&sHid[k * HSTRIDE + (mg << 2)];
        float4 w = sW24[(k << 4) + jg];
        ull pa0, pa1, pa2, pa3, q0, q1;
        PK(pa0, a.x, a.x); PK(pa1, a.y, a.y); PK(pa2, a.z, a.z); PK(pa3, a.w, a.w);
        PK(q0, w.x, w.y); PK(q1, w.z, w.w);
        FMA2(c2[0][0], pa0, q0, c2[0][0]); FMA2(c2[0][1], pa0, q1, c2[0][1]);
        FMA2(c2[1][0], pa1, q0, c2[1][0]); FMA2(c2[1][1], pa1, q1, c2[1][1]);
        FMA2(c2[2][0], pa2, q0, c2[2][0]); FMA2(c2[2][1], pa2, q1, c2[2][1]);
        FMA2(c2[3][0], pa3, q0, c2[3][0]); FMA2(c2[3][1], pa3, q1, c2[3][1]);
    }

    // ---- fused epilogue ----
    const int j0 = jg << 2;
    float o[4][4];
    {
        float b0 = sb2[j0], bb1 = sb2[j0 + 1], bb2 = sb2[j0 + 2], bb3 = sb2[j0 + 3];
        float4 psum, psq;
        float* ps = (float*)&psum;
        float* pq = (float*)&psq;
        #pragma unroll
        for (int mi = 0; mi < 4; mi++) {
            int n = blockIdx.x * TM + (mg << 2) + mi;
            UPK(o[mi][0], o[mi][1], c2[mi][0]);
            UPK(o[mi][2], o[mi][3], c2[mi][1]);
            o[mi][0] += b0; o[mi][1] += bb1; o[mi][2] += bb2; o[mi][3] += bb3;
            if (MODE == 1) {
                int nc = (n < N) ? n : (N - 1);
                float4 r = *(const float4*)&res[nc * H + j0];
                o[mi][0] += r.x; o[mi][1] += r.y; o[mi][2] += r.z; o[mi][3] += r.w;
            } else {
                if (n < N)
                    *(float4*)&out[n * H + j0] = make_float4(o[mi][0], o[mi][1], o[mi][2], o[mi][3]);
            }
            float s = (o[mi][0] + o[mi][1]) + (o[mi][2] + o[mi][3]);
            float q = (o[mi][0] * o[mi][0] + o[mi][1] * o[mi][1])
                    + (o[mi][2] * o[mi][2] + o[mi][3] * o[mi][3]);
            ps[mi] = s; pq[mi] = q;
        }
        *(float4*)&sRs[jg * TM + (mg << 2)] = psum;
        *(float4*)&sRq[jg * TM + (mg << 2)] = psq;
    }
    __syncthreads();
    if (tid < TM) {
        float s = 0.f, q = 0.f;
        #pragma unroll
        for (int g = 0; g < 16; g++) { s += sRs[g * TM + tid]; q += sRq[g * TM + tid]; }
        float mu = s * (1.f / 64.f);
        float var = q * (1.f / 64.f) - mu * mu;
        sMu[tid] = mu;
        sInv[tid] = rsqrtf(var + 1e-5f);
    }
    __syncthreads();

    if (MODE == 0) {
        // write relu(LN64(h1)) to out2 AND the layer-2 fp16 P precompute
        float c = __ldg(tp) * LOG2E;
        float g0 = sgx[j0], g1v = sgx[j0 + 1], g2v = sgx[j0 + 2], g3v = sgx[j0 + 3];
        float x0 = sbx[j0], x1 = sbx[j0 + 1], x2 = sbx[j0 + 2], x3 = sbx[j0 + 3];
        #pragma unroll
        for (int mi = 0; mi < 4; mi++) {
            int n = blockIdx.x * TM + (mg << 2) + mi;
            if (n < N) {
                float mu = sMu[(mg << 2) + mi], iv = sInv[(mg << 2) + mi];
                float4 y;
                y.x = fmaxf((o[mi][0] - mu) * iv * g0 + x0, 0.f);
                y.y = fmaxf((o[mi][1] - mu) * iv * g1v + x1, 0.f);
                y.z = fmaxf((o[mi][2] - mu) * iv * g2v + x2, 0.f);
                y.w = fmaxf((o[mi][3] - mu) * iv * g3v + x3, 0.f);
                *(float4*)&out2[n * H + j0] = y;
                float vx = y.x + 1e-7f, vy = y.y + 1e-7f;
                float vz = y.z + 1e-7f, vw = y.w + 1e-7f;
                float wx = exp2f(vx * c), wy = exp2f(vy * c);
                float wz = exp2f(vz * c), ww = exp2f(vw * c);
                __half2 h0 = __floats2half2_rn(vx * wx, wx);
                __half2 h1 = __floats2half2_rn(vy * wy, wy);
                __half2 h2 = __floats2half2_rn(vz * wz, wz);
                __half2 h3 = __floats2half2_rn(vw * ww, ww);
                uint4 u;
                u.x = *(unsigned*)&h0; u.y = *(unsigned*)&h1;
                u.z = *(unsigned*)&h2; u.w = *(unsigned*)&h3;
                Pout[n * 16 + jg] = u;
            }
        }
    } else {
        // final head: partial dot of relu(LN64(h2)) with W_lin
        float g0 = sgx[j0], g1v = sgx[j0 + 1], g2v = sgx[j0 + 2], g3v = sgx[j0 + 3];
        float x0 = sbx[j0], x1 = sbx[j0 + 1], x2 = sbx[j0 + 2], x3 = sbx[j0 + 3];
        float w0 = sWl[j0], w1 = sWl[j0 + 1], w2 = sWl[j0 + 2], w3 = sWl[j0 + 3];
        float4 pdot;
        float* pd = (float*)&pdot;
        #pragma unroll
        for (int mi = 0; mi < 4; mi++) {
            float mu = sMu[(mg << 2) + mi], iv = sInv[(mg << 2) + mi];
            float y0 = fmaxf((o[mi][0] - mu) * iv * g0 + x0, 0.f);
            float y1 = fmaxf((o[mi][1] - mu) * iv * g1v + x1, 0.f);
            float y2 = fmaxf((o[mi][2] - mu) * iv * g2v + x2, 0.f);
            float y3 = fmaxf((o[mi][3] - mu) * iv * g3v + x3, 0.f);
            pd[mi] = (y0 * w0 + y1 * w1) + (y2 * w2 + y3 * w3);
        }
        *(float4*)&sRs[jg * TM + (mg << 2)] = pdot;
        __syncthreads();
        if (tid < TM) {
            int n = blockIdx.x * TM + tid;
            if (n < N) {
                float p = 0.f;
                #pragma unroll
                for (int g = 0; g < 16; g++) p += sRs[g * TM + tid];
                float logit = p + __ldg(bl);
                out[n]     = 1.f / (1.f + expf(-logit));
                out[N + n] = logit;
            }
        }
    }
}

// ---------------- host launcher ----------------
extern "C" void kernel_launch(void* const* d_in, const int* in_sizes, int n_in,
                              void* d_out, int out_size) {
    const float* x      = (const float*)d_in[0];
    const int*   eidx   = (const int*)d_in[1];
    const float* W_enc  = (const float*)d_in[2];
    const float* b_enc  = (const float*)d_in[3];
    const float* t1     = (const float*)d_in[4];
    const float* W1a    = (const float*)d_in[5];
    const float* b1a    = (const float*)d_in[6];
    const float* g1a    = (const float*)d_in[7];
    const float* be1a   = (const float*)d_in[8];
    const float* W1b    = (const float*)d_in[9];
    const float* b1b    = (const float*)d_in[10];
    const float* g_n1   = (const float*)d_in[11];
    const float* b_n1   = (const float*)d_in[12];
    const float* t2     = (const float*)d_in[13];
    const float* W2a    = (const float*)d_in[14];
    const float* b2a    = (const float*)d_in[15];
    const float* g2a    = (const float*)d_in[16];
    const float* be2a   = (const float*)d_in[17];
    const float* W2b    = (const float*)d_in[18];
    const float* b2b    = (const float*)d_in[19];
    const float* g_n0   = (const float*)d_in[20];
    const float* b_n0   = (const float*)d_in[21];
    const float* W_lin  = (const float*)d_in[22];
    const float* b_lin  = (const float*)d_in[23];
    float* out = (float*)d_out;

    int N = in_sizes[0] / 16;
    int E = in_sizes[1] / 2;
    if (N > MAXN) N = MAXN;
    if (E > MAXE) E = MAXE;
    const int* src = eidx;
    const int* dst = eidx + E;

    float *pA, *pB, *pC, *pE;
    uint4* pP;
    int *pCnt, *pAdj;
    cudaGetSymbolAddress((void**)&pA, d_bufA);
    cudaGetSymbolAddress((void**)&pB, d_bufB);
    cudaGetSymbolAddress((void**)&pC, d_bufC);
    cudaGetSymbolAddress((void**)&pE, d_bufE);
    cudaGetSymbolAddress((void**)&pP, d_P);
    cudaGetSymbolAddress((void**)&pCnt, d_cnt);
    cudaGetSymbolAddress((void**)&pAdj, d_adj);

    const int mlp_smem = (8192 * 3 + 128 * HSTRIDE + 2048 * 2 + 128 * 2 + 128 * 3
                          + 64 + 64 * 3) * (int)sizeof(float);
    cudaFuncSetAttribute(k_mlp<0>, cudaFuncAttributeMaxDynamicSharedMemorySize, mlp_smem);
    cudaFuncSetAttribute(k_mlp<1>, cudaFuncAttributeMaxDynamicSharedMemorySize, mlp_smem);

    int mlp_grid = (N + TM - 1) / TM;
    int agg_grid = (N * 32 + 255) / 256;

    // (1) encoder -> h0 + fused layer-1 P + zero cnt
    k_encoder<<<(N * 16 + 255) / 256, 256>>>(x, W_enc, b_enc, pE, pP, t1, pCnt, N);
    // (2) bucket placement
    k_place<<<(E + 255) / 256, 256>>>(src, dst, pCnt, pAdj, E);
    // (3) layer-1 aggregation
    k_agg<<<agg_grid, 256>>>((const float4*)pE, (float4*)pA, pP, pCnt, pAdj, N);
    // (4) MLP1 -> h1 (bufB) + relu(LN(h1)) (bufC) + layer-2 P
    k_mlp<0><<<mlp_grid, 512, mlp_smem>>>(pA, pB, pC, (const float*)nullptr,
                                          W1a, b1a, g1a, be1a, W1b, b1b,
                                          g_n1, b_n1, (const float*)nullptr,
                                          (const float*)nullptr, pP, t2, N);
    // (5) layer-2 aggregation
    k_agg<<<agg_grid, 256>>>((const float4*)pC, (float4*)pA, pP, pCnt, pAdj, N);
    // (6) MLP2 + residual + final head -> out  [profiled slot]
    k_mlp<1><<<mlp_grid, 512, mlp_smem>>>(pA, out, (float*)nullptr, pB,
                                          W2a, b2a, g2a, be2a, W2b, b2b,
                                          g_n0, b_n0, W_lin, b_lin,
                                          (uint4*)nullptr, (const float*)nullptr, N);
}

// round 13
// speedup vs baseline: 1.0596x; 1.0596x over previous
#include <cuda_runtime.h>
#include <cuda_fp16.h>
#include <cstdint>
#include <math.h>

#define MAXN 100000
#define MAXE 1600000
#define PAD 64
#define TM 128
#define LOG2E 1.44269504088896f

typedef unsigned long long ull;

// ---------------- scratch (static device globals; no allocs) ----------------
__device__ float  d_bufA[MAXN * 64];     // agg output (both layers)
__device__ float  d_bufB[MAXN * 64];     // h1
__device__ float  d_bufC[MAXN * 64];     // relu(LN(h1))
__device__ float  d_bufE[MAXN * 64];     // h0
__device__ uint4  d_P[MAXN * 16];        // per-node (vw,w) half2 pairs
__device__ int    d_cnt[MAXN];
__device__ int    d_adj[MAXN * PAD];
__device__ __half d_hidT[128 * MAXN];    // transposed fp16 hidden [k][n]

// packed fp32x2 helpers (sm_103a FFMA2 path)
#define PK(d, lo, hi)  asm("mov.b64 %0, {%1, %2};" : "=l"(d) : "f"(lo), "f"(hi))
#define UPK(lo, hi, s) asm("mov.b64 {%0, %1}, %2;" : "=f"(lo), "=f"(hi) : "l"(s))
#define FMA2(d, a, b, c) asm("fma.rn.f32x2 %0, %1, %2, %3;" : "=l"(d) : "l"(a), "l"(b), "l"(c))

// ---------------- encoder: h = x @ W_enc + b_enc (+ zero cnt) ---------------
__global__ void k_encoder(const float* __restrict__ x, const float* __restrict__ W,
                          const float* __restrict__ b, float* __restrict__ h,
                          int* __restrict__ cnt, int N) {
    __shared__ float4 sW[16 * 16];
    __shared__ float4 sB[16];
    int tid = threadIdx.x;
    if (tid < 256) sW[tid] = ((const float4*)W)[tid];
    if (tid < 16)  sB[tid] = ((const float4*)b)[tid];
    __syncthreads();
    int idx = blockIdx.x * blockDim.x + threadIdx.x;
    if (idx < N) cnt[idx] = 0;
    int total = N * 16;
    if (idx >= total) return;
    int n = idx >> 4, q = idx & 15;
    const float4* xr = (const float4*)(x + n * 16);
    float4 x0 = xr[0], x1 = xr[1], x2 = xr[2], x3 = xr[3];
    float4 acc = sB[q];
    #define ESTEP(xv, kk) { float4 w = sW[(kk) * 16 + q]; \
        acc.x += (xv) * w.x; acc.y += (xv) * w.y; acc.z += (xv) * w.z; acc.w += (xv) * w.w; }
    ESTEP(x0.x, 0)  ESTEP(x0.y, 1)  ESTEP(x0.z, 2)  ESTEP(x0.w, 3)
    ESTEP(x1.x, 4)  ESTEP(x1.y, 5)  ESTEP(x1.z, 6)  ESTEP(x1.w, 7)
    ESTEP(x2.x, 8)  ESTEP(x2.y, 9)  ESTEP(x2.z, 10) ESTEP(x2.w, 11)
    ESTEP(x3.x, 12) ESTEP(x3.y, 13) ESTEP(x3.z, 14) ESTEP(x3.w, 15)
    #undef ESTEP
    ((float4*)h)[idx] = acc;
}

// ---------------- bucket placement ----------------
__global__ void k_place(const int* __restrict__ src, const int* __restrict__ dst,
                        int* __restrict__ cnt, int* __restrict__ adj, int E) {
    int e = blockIdx.x * blockDim.x + threadIdx.x;
    if (e >= E) return;
    int d = dst[e];
    int p = atomicAdd(&cnt[d], 1);
    if (p < PAD) adj[(d << 6) + p] = src[e];
}

// ---------------- per-node softmax precompute ----------------
__global__ void k_prep(const float4* __restrict__ feat4, uint4* __restrict__ P,
                       const float* __restrict__ tptr, int N16) {
    int idx = blockIdx.x * blockDim.x + threadIdx.x;
    if (idx >= N16) return;
    float c = __ldg(tptr) * LOG2E;
    float4 v = feat4[idx];
    v.x = fmaxf(v.x, 0.f) + 1e-7f;
    v.y = fmaxf(v.y, 0.f) + 1e-7f;
    v.z = fmaxf(v.z, 0.f) + 1e-7f;
    v.w = fmaxf(v.w, 0.f) + 1e-7f;
    float wx = exp2f(v.x * c), wy = exp2f(v.y * c);
    float wz = exp2f(v.z * c), ww = exp2f(v.w * c);
    __half2 h0 = __floats2half2_rn(v.x * wx, wx);
    __half2 h1 = __floats2half2_rn(v.y * wy, wy);
    __half2 h2 = __floats2half2_rn(v.z * wz, wz);
    __half2 h3 = __floats2half2_rn(v.w * ww, ww);
    uint4 u;
    u.x = *(unsigned*)&h0; u.y = *(unsigned*)&h1;
    u.z = *(unsigned*)&h2; u.w = *(unsigned*)&h3;
    P[idx] = u;
}

// ---------------- aggregation: fp16 P gather (round-6 best) ----------------
#define ACCP(p) { \
    float2 q0 = __half22float2(*(__half2*)&(p).x); \
    float2 q1 = __half22float2(*(__half2*)&(p).y); \
    float2 q2 = __half22float2(*(__half2*)&(p).z); \
    float2 q3 = __half22float2(*(__half2*)&(p).w); \
    n0 += q0.x; d0 += q0.y; n1 += q1.x; d1 += q1.y; \
    n2 += q2.x; d2 += q2.y; n3 += q3.x; d3 += q3.y; }

__global__ void __launch_bounds__(256)
k_agg(const float4* __restrict__ feat4, float4* __restrict__ out4,
      const uint4* __restrict__ P, const int* __restrict__ cnt,
      const int* __restrict__ adj, int N) {
    int gid = (blockIdx.x * 256 + threadIdx.x) >> 4;
    if (gid >= N) return;
    int f = threadIdx.x & 15;
    int deg = cnt[gid]; deg = min(deg, PAD);
    const int4* lst4 = (const int4*)(adj + (gid << 6));
    float n0 = 0.f, n1 = 0.f, n2 = 0.f, n3 = 0.f;
    float d0 = 0.f, d1 = 0.f, d2 = 0.f, d3 = 0.f;
    int full = deg >> 2;
    for (int c = 0; c < full; c++) {
        int4 s = lst4[c];
        uint4 p0 = P[s.x * 16 + f];
        uint4 p1 = P[s.y * 16 + f];
        uint4 p2 = P[s.z * 16 + f];
        uint4 p3 = P[s.w * 16 + f];
        ACCP(p0); ACCP(p1); ACCP(p2); ACCP(p3);
    }
    int r = deg & 3;
    if (r) {
        int4 s = lst4[full];
        uint4 p0 = P[s.x * 16 + f]; ACCP(p0);
        if (r > 1) { uint4 p1 = P[s.y * 16 + f]; ACCP(p1); }
        if (r > 2) { uint4 p2 = P[s.z * 16 + f]; ACCP(p2); }
    }
    float4 self = feat4[gid * 16 + f];
    float4 o;
    o.x = n0 / (d0 + 1e-16f) + self.x;
    o.y = n1 / (d1 + 1e-16f) + self.y;
    o.z = n2 / (d2 + 1e-16f) + self.z;
    o.w = n3 / (d3 + 1e-16f) + self.w;
    out4[gid * 16 + f] = o;
}

// ---------------- MLP kernel A: GEMM1 + LN128 + ReLU -> hidT fp16 -----------
// smem floats: sW1[8192] sIn[8192] sRs[2048] sRq[2048] sMu[128] sInv[128]
//              sb1[128] sg1[128] sbe1[128]  (total 21120 f = 84480 B)
#define A_W1  0
#define A_IN  8192
#define A_RS  16384
#define A_RQ  18432
#define A_MU  20480
#define A_INV 20608
#define A_B1  20736
#define A_G1  20864
#define A_BE1 20992
#define A_TOT (21120 * 4)

__global__ void __launch_bounds__(512, 2)
k_mlpA(const float* __restrict__ in, __half* __restrict__ hidT,
       const float* __restrict__ W1, const float* __restrict__ b1,
       const float* __restrict__ g1, const float* __restrict__ be1, int N) {
    extern __shared__ float sm[];
    const int tid = threadIdx.x;
    const int mg  = tid & 31;
    const int jg  = tid >> 5;

    {
        const float4* W14 = (const float4*)W1;
        float4* sW14 = (float4*)(sm + A_W1);
        #pragma unroll
        for (int i = 0; i < 4; i++) sW14[tid + i * 512] = W14[tid + i * 512];
        if (tid < 128) {
            sm[A_B1 + tid]  = b1[tid];
            sm[A_G1 + tid]  = g1[tid];
            sm[A_BE1 + tid] = be1[tid];
        }
    }
    {
        int nl = tid & 127;
        int q  = tid >> 7;
        int n  = blockIdx.x * TM + nl;
        if (n >= N) n = N - 1;
        const float4* ip = (const float4*)(in + (size_t)n * 64);
        #pragma unroll
        for (int i = 0; i < 4; i++) {
            float4 v = ip[q * 4 + i];
            int k0 = (q * 4 + i) * 4;
            sm[A_IN + (k0 + 0) * TM + nl] = v.x;
            sm[A_IN + (k0 + 1) * TM + nl] = v.y;
            sm[A_IN + (k0 + 2) * TM + nl] = v.z;
            sm[A_IN + (k0 + 3) * TM + nl] = v.w;
        }
    }
    __syncthreads();

    // GEMM1: [128 x 64] @ [64 x 128]; thread tile 4m x 8j
    ull acc[4][4];
    #pragma unroll
    for (int a = 0; a < 4; a++)
        #pragma unroll
        for (int bq = 0; bq < 4; bq++) acc[a][bq] = 0ull;

    const float4* sIn4 = (const float4*)(sm + A_IN);
    const float4* sW14 = (const float4*)(sm + A_W1);
    #pragma unroll 8
    for (int k = 0; k < 64; k++) {
        float4 a  = sIn4[k * 32 + mg];
        float4 w0 = sW14[k * 32 + (jg << 1)];
        float4 w1 = sW14[k * 32 + (jg << 1) + 1];
        ull pa0, pa1, pa2, pa3, q0, q1, q2, q3;
        PK(pa0, a.x, a.x); PK(pa1, a.y, a.y); PK(pa2, a.z, a.z); PK(pa3, a.w, a.w);
        PK(q0, w0.x, w0.y); PK(q1, w0.z, w0.w); PK(q2, w1.x, w1.y); PK(q3, w1.z, w1.w);
        FMA2(acc[0][0], pa0, q0, acc[0][0]); FMA2(acc[0][1], pa0, q1, acc[0][1]);
        FMA2(acc[0][2], pa0, q2, acc[0][2]); FMA2(acc[0][3], pa0, q3, acc[0][3]);
        FMA2(acc[1][0], pa1, q0, acc[1][0]); FMA2(acc[1][1], pa1, q1, acc[1][1]);
        FMA2(acc[1][2], pa1, q2, acc[1][2]); FMA2(acc[1][3], pa1, q3, acc[1][3]);
        FMA2(acc[2][0], pa2, q0, acc[2][0]); FMA2(acc[2][1], pa2, q1, acc[2][1]);
        FMA2(acc[2][2], pa2, q2, acc[2][2]); FMA2(acc[2][3], pa2, q3, acc[2][3]);
        FMA2(acc[3][0], pa3, q0, acc[3][0]); FMA2(acc[3][1], pa3, q1, acc[3][1]);
        FMA2(acc[3][2], pa3, q2, acc[3][2]); FMA2(acc[3][3], pa3, q3, acc[3][3]);
    }

    // bias + per-node partial LN sums (over 128 hidden)
    float hreg[4][8];
    {
        float4 psum, psq;
        float* ps = (float*)&psum;
        float* pq = (float*)&psq;
        #pragma unroll
        for (int mi = 0; mi < 4; mi++) {
            float s = 0.f, q = 0.f;
            #pragma unroll
            for (int jp = 0; jp < 4; jp++) {
                float lo, hi;
                UPK(lo, hi, acc[mi][jp]);
                lo += sm[A_B1 + (jg << 3) + 2 * jp];
                hi += sm[A_B1 + (jg << 3) + 2 * jp + 1];
                hreg[mi][2 * jp] = lo; hreg[mi][2 * jp + 1] = hi;
                s += lo + hi; q += lo * lo + hi * hi;
            }
            ps[mi] = s; pq[mi] = q;
        }
        *(float4*)&sm[A_RS + jg * TM + (mg << 2)] = psum;
        *(float4*)&sm[A_RQ + jg * TM + (mg << 2)] = psq;
    }
    __syncthreads();
    if (tid < TM) {
        float s = 0.f, q = 0.f;
        #pragma unroll
        for (int g = 0; g < 16; g++) { s += sm[A_RS + g * TM + tid]; q += sm[A_RQ + g * TM + tid]; }
        float mu = s * (1.f / 128.f);
        float var = q * (1.f / 128.f) - mu * mu;
        sm[A_MU + tid]  = mu;
        sm[A_INV + tid] = rsqrtf(var + 1e-5f);
    }
    __syncthreads();

    // LN + ReLU -> fp16, store transposed hidT[j][n]
    {
        float mu[4], iv[4];
        int n0 = blockIdx.x * TM + (mg << 2);
        #pragma unroll
        for (int mi = 0; mi < 4; mi++) {
            mu[mi] = sm[A_MU + (mg << 2) + mi];
            iv[mi] = sm[A_INV + (mg << 2) + mi];
        }
        #pragma unroll
        for (int jj = 0; jj < 8; jj++) {
            int j = (jg << 3) + jj;
            float gg = sm[A_G1 + j], bb = sm[A_BE1 + j];
            float y0 = fmaxf((hreg[0][jj] - mu[0]) * iv[0] * gg + bb, 0.f);
            float y1 = fmaxf((hreg[1][jj] - mu[1]) * iv[1] * gg + bb, 0.f);
            float y2 = fmaxf((hreg[2][jj] - mu[2]) * iv[2] * gg + bb, 0.f);
            float y3 = fmaxf((hreg[3][jj] - mu[3]) * iv[3] * gg + bb, 0.f);
            __half2 hlo = __floats2half2_rn(y0, y1);
            __half2 hhi = __floats2half2_rn(y2, y3);
            __half* dstp = hidT + (size_t)j * MAXN + n0;
            if (n0 + 3 < N) {
                uint2 u;
                u.x = *(unsigned*)&hlo; u.y = *(unsigned*)&hhi;
                *(uint2*)dstp = u;
            } else {
                if (n0 + 0 < N) dstp[0] = __low2half(hlo);
                if (n0 + 1 < N) dstp[1] = __high2half(hlo);
                if (n0 + 2 < N) dstp[2] = __low2half(hhi);
                if (n0 + 3 < N) dstp[3] = __high2half(hhi);
            }
        }
    }
}

// ---------------- MLP kernel B: GEMM2 (hid fp16) + fused epilogue -----------
// smem floats: sW2[8192] sHid(half 16384 -> 8192 f) sRs[2048] sRq[2048]
//              sMu[128] sInv[128] sb2[64] sgx[64] sbx[64] sWl[64]  = 20992 f
#define B_W2  0
#define B_HID 8192
#define B_RS  16384
#define B_RQ  18432
#define B_MU  20480
#define B_INV 20608
#define B_B2  20736
#define B_GX  20800
#define B_BX  20864
#define B_WL  20928
#define B_TOT (20992 * 4)

template <int MODE>
__global__ void __launch_bounds__(512, 2)
k_mlpB(const __half* __restrict__ hidT, float* __restrict__ out,
       float* __restrict__ out2, const float* __restrict__ res,
       const float* __restrict__ W2, const float* __restrict__ b2,
       const float* __restrict__ gx, const float* __restrict__ bx,
       const float* __restrict__ Wl, const float* __restrict__ bl,
       uint4* __restrict__ Pout, const float* __restrict__ tp, int N) {
    extern __shared__ float sm[];
    const int tid = threadIdx.x;
    const int mg  = tid & 31;
    const int jg  = tid >> 5;

    {
        const float4* W24 = (const float4*)W2;
        float4* sW24 = (float4*)(sm + B_W2);
        #pragma unroll
        for (int i = 0; i < 4; i++) sW24[tid + i * 512] = W24[tid + i * 512];
        if (tid < 64) {
            sm[B_B2 + tid] = b2[tid];
            sm[B_GX + tid] = gx[tid];
            sm[B_BX + tid] = bx[tid];
            sm[B_WL + tid] = (MODE == 1) ? Wl[tid] : 0.f;
        }
        // load hid tile: rows k = tid>>2, 4 uint4 chunks each
        int kk = tid >> 2;
        int cc = tid & 3;
        const uint4* gh = (const uint4*)(hidT + (size_t)kk * MAXN + blockIdx.x * TM);
        uint4* sh = (uint4*)(sm + B_HID);
        #pragma unroll
        for (int i = 0; i < 4; i++)
            sh[kk * 16 + cc * 4 + i] = gh[cc * 4 + i];
    }
    __syncthreads();

    // GEMM2: [128 x 128(fp16)] @ [128 x 64]; thread tile 4m x 4j
    ull c2[4][2];
    #pragma unroll
    for (int a = 0; a < 4; a++) { c2[a][0] = 0ull; c2[a][1] = 0ull; }

    const float4* sW24 = (const float4*)(sm + B_W2);
    const __half2* sh2 = (const __half2*)(sm + B_HID);
    #pragma unroll 8
    for (int k = 0; k < 128; k++) {
        __half2 ha = sh2[k * 64 + (mg << 1)];
        __half2 hb = sh2[k * 64 + (mg << 1) + 1];
        float2 fa = __half22float2(ha);
        float2 fb = __half22float2(hb);
        float4 w = sW24[(k << 4) + jg];
        ull pa0, pa1, pa2, pa3, q0, q1;
        PK(pa0, fa.x, fa.x); PK(pa1, fa.y, fa.y);
        PK(pa2, fb.x, fb.x); PK(pa3, fb.y, fb.y);
        PK(q0, w.x, w.y); PK(q1, w.z, w.w);
        FMA2(c2[0][0], pa0, q0, c2[0][0]); FMA2(c2[0][1], pa0, q1, c2[0][1]);
        FMA2(c2[1][0], pa1, q0, c2[1][0]); FMA2(c2[1][1], pa1, q1, c2[1][1]);
        FMA2(c2[2][0], pa2, q0, c2[2][0]); FMA2(c2[2][1], pa2, q1, c2[2][1]);
        FMA2(c2[3][0], pa3, q0, c2[3][0]); FMA2(c2[3][1], pa3, q1, c2[3][1]);
    }

    // epilogue: bias (+res), LN64 stats
    const int j0 = jg << 2;
    float o[4][4];
    {
        float b0 = sm[B_B2 + j0],     bb1 = sm[B_B2 + j0 + 1];
        float bb2 = sm[B_B2 + j0 + 2], bb3 = sm[B_B2 + j0 + 3];
        float4 psum, psq;
        float* ps = (float*)&psum;
        float* pq = (float*)&psq;
        #pragma unroll
        for (int mi = 0; mi < 4; mi++) {
            int n = blockIdx.x * TM + (mg << 2) + mi;
            UPK(o[mi][0], o[mi][1], c2[mi][0]);
            UPK(o[mi][2], o[mi][3], c2[mi][1]);
            o[mi][0] += b0; o[mi][1] += bb1; o[mi][2] += bb2; o[mi][3] += bb3;
            if (MODE == 1) {
                int nc = (n < N) ? n : (N - 1);
                float4 r = *(const float4*)&res[(size_t)nc * 64 + j0];
                o[mi][0] += r.x; o[mi][1] += r.y; o[mi][2] += r.z; o[mi][3] += r.w;
            } else {
                if (n < N)
                    *(float4*)&out[(size_t)n * 64 + j0] =
                        make_float4(o[mi][0], o[mi][1], o[mi][2], o[mi][3]);
            }
            float s = (o[mi][0] + o[mi][1]) + (o[mi][2] + o[mi][3]);
            float q = (o[mi][0] * o[mi][0] + o[mi][1] * o[mi][1])
                    + (o[mi][2] * o[mi][2] + o[mi][3] * o[mi][3]);
            ps[mi] = s; pq[mi] = q;
        }
        *(float4*)&sm[B_RS + jg * TM + (mg << 2)] = psum;
        *(float4*)&sm[B_RQ + jg * TM + (mg << 2)] = psq;
    }
    __syncthreads();
    if (tid < TM) {
        float s = 0.f, q = 0.f;
        #pragma unroll
        for (int g = 0; g < 16; g++) { s += sm[B_RS + g * TM + tid]; q += sm[B_RQ + g * TM + tid]; }
        float mu = s * (1.f / 64.f);
        float var = q * (1.f / 64.f) - mu * mu;
        sm[B_MU + tid]  = mu;
        sm[B_INV + tid] = rsqrtf(var + 1e-5f);
    }
    __syncthreads();

    if (MODE == 0) {
        // write relu(LN64(h1)) to out2 AND the layer-2 fp16 P precompute
        float cP = __ldg(tp) * LOG2E;
        float g0 = sm[B_GX + j0],     g1v = sm[B_GX + j0 + 1];
        float g2v = sm[B_GX + j0 + 2], g3v = sm[B_GX + j0 + 3];
        float x0 = sm[B_BX + j0],     x1 = sm[B_BX + j0 + 1];
        float x2 = sm[B_BX + j0 + 2], x3 = sm[B_BX + j0 + 3];
        #pragma unroll
        for (int mi = 0; mi < 4; mi++) {
            int n = blockIdx.x * TM + (mg << 2) + mi;
            if (n < N) {
                float mu = sm[B_MU + (mg << 2) + mi], iv = sm[B_INV + (mg << 2) + mi];
                float4 y;
                y.x = fmaxf((o[mi][0] - mu) * iv * g0 + x0, 0.f);
                y.y = fmaxf((o[mi][1] - mu) * iv * g1v + x1, 0.f);
                y.z = fmaxf((o[mi][2] - mu) * iv * g2v + x2, 0.f);
                y.w = fmaxf((o[mi][3] - mu) * iv * g3v + x3, 0.f);
                *(float4*)&out2[(size_t)n * 64 + j0] = y;
                float vx = y.x + 1e-7f, vy = y.y + 1e-7f;
                float vz = y.z + 1e-7f, vw = y.w + 1e-7f;
                float wx = exp2f(vx * cP), wy = exp2f(vy * cP);
                float wz = exp2f(vz * cP), ww = exp2f(vw * cP);
                __half2 a0 = __floats2half2_rn(vx * wx, wx);
                __half2 a1 = __floats2half2_rn(vy * wy, wy);
                __half2 a2 = __floats2half2_rn(vz * wz, wz);
                __half2 a3 = __floats2half2_rn(vw * ww, ww);
                uint4 u;
                u.x = *(unsigned*)&a0; u.y = *(unsigned*)&a1;
                u.z = *(unsigned*)&a2; u.w = *(unsigned*)&a3;
                Pout[(size_t)n * 16 + jg] = u;
            }
        }
    } else {
        // final head: partial dot of relu(LN64(h2)) with W_lin
        float g0 = sm[B_GX + j0],     g1v = sm[B_GX + j0 + 1];
        float g2v = sm[B_GX + j0 + 2], g3v = sm[B_GX + j0 + 3];
        float x0 = sm[B_BX + j0],     x1 = sm[B_BX + j0 + 1];
        float x2 = sm[B_BX + j0 + 2], x3 = sm[B_BX + j0 + 3];
        float w0 = sm[B_WL + j0],     w1 = sm[B_WL + j0 + 1];
        float w2 = sm[B_WL + j0 + 2], w3 = sm[B_WL + j0 + 3];
        float4 pdot;
        float* pd = (float*)&pdot;
        #pragma unroll
        for (int mi = 0; mi < 4; mi++) {
            float mu = sm[B_MU + (mg << 2) + mi], iv = sm[B_INV + (mg << 2) + mi];
            float y0 = fmaxf((o[mi][0] - mu) * iv * g0 + x0, 0.f);
            float y1 = fmaxf((o[mi][1] - mu) * iv * g1v + x1, 0.f);
            float y2 = fmaxf((o[mi][2] - mu) * iv * g2v + x2, 0.f);
            float y3 = fmaxf((o[mi][3] - mu) * iv * g3v + x3, 0.f);
            pd[mi] = (y0 * w0 + y1 * w1) + (y2 * w2 + y3 * w3);
        }
        *(float4*)&sm[B_RS + jg * TM + (mg << 2)] = pdot;
        __syncthreads();
        if (tid < TM) {
            int n = blockIdx.x * TM + tid;
            if (n < N) {
                float p = 0.f;
                #pragma unroll
                for (int g = 0; g < 16; g++) p += sm[B_RS + g * TM + tid];
                float logit = p + __ldg(bl);
                out[n]     = 1.f / (1.f + expf(-logit));
                out[N + n] = logit;
            }
        }
    }
}

// ---------------- host launcher ----------------
extern "C" void kernel_launch(void* const* d_in, const int* in_sizes, int n_in,
                              void* d_out, int out_size) {
    const float* x      = (const float*)d_in[0];
    const int*   eidx   = (const int*)d_in[1];
    const float* W_enc  = (const float*)d_in[2];
    const float* b_enc  = (const float*)d_in[3];
    const float* t1     = (const float*)d_in[4];
    const float* W1a    = (const float*)d_in[5];
    const float* b1a    = (const float*)d_in[6];
    const float* g1a    = (const float*)d_in[7];
    const float* be1a   = (const float*)d_in[8];
    const float* W1b    = (const float*)d_in[9];
    const float* b1b    = (const float*)d_in[10];
    const float* g_n1   = (const float*)d_in[11];
    const float* b_n1   = (const float*)d_in[12];
    const float* t2     = (const float*)d_in[13];
    const float* W2a    = (const float*)d_in[14];
    const float* b2a    = (const float*)d_in[15];
    const float* g2a    = (const float*)d_in[16];
    const float* be2a   = (const float*)d_in[17];
    const float* W2b    = (const float*)d_in[18];
    const float* b2b    = (const float*)d_in[19];
    const float* g_n0   = (const float*)d_in[20];
    const float* b_n0   = (const float*)d_in[21];
    const float* W_lin  = (const float*)d_in[22];
    const float* b_lin  = (const float*)d_in[23];
    float* out = (float*)d_out;

    int N = in_sizes[0] / 16;
    int E = in_sizes[1] / 2;
    if (N > MAXN) N = MAXN;
    if (E > MAXE) E = MAXE;
    const int* src = eidx;
    const int* dst = eidx + E;

    float *pA, *pB, *pC, *pE;
    uint4* pP;
    __half* pH;
    int *pCnt, *pAdj;
    cudaGetSymbolAddress((void**)&pA, d_bufA);
    cudaGetSymbolAddress((void**)&pB, d_bufB);
    cudaGetSymbolAddress((void**)&pC, d_bufC);
    cudaGetSymbolAddress((void**)&pE, d_bufE);
    cudaGetSymbolAddress((void**)&pP, d_P);
    cudaGetSymbolAddress((void**)&pH, d_hidT);
    cudaGetSymbolAddress((void**)&pCnt, d_cnt);
    cudaGetSymbolAddress((void**)&pAdj, d_adj);

    cudaFuncSetAttribute(k_mlpA, cudaFuncAttributeMaxDynamicSharedMemorySize, A_TOT);
    cudaFuncSetAttribute(k_mlpB<0>, cudaFuncAttributeMaxDynamicSharedMemorySize, B_TOT);
    cudaFuncSetAttribute(k_mlpB<1>, cudaFuncAttributeMaxDynamicSharedMemorySize, B_TOT);

    int mlp_grid = (N + TM - 1) / TM;
    int agg_grid = (N * 16 + 255) / 256;

    // (1) encoder -> h0 (+ zero cnt)
    k_encoder<<<(N * 16 + 255) / 256, 256>>>(x, W_enc, b_enc, pE, pCnt, N);
    // (2) bucket placement
    k_place<<<(E + 255) / 256, 256>>>(src, dst, pCnt, pAdj, E);
    // (3) layer-1 fp16 P precompute
    k_prep<<<(N * 16 + 255) / 256, 256>>>((const float4*)pE, pP, t1, N * 16);
    // (4) layer-1 aggregation  [profiled slot — expect ~47us parity]
    k_agg<<<agg_grid, 256>>>((const float4*)pE, (float4*)pA, pP, pCnt, pAdj, N);
    // (5) MLP1-A: GEMM1 + LN + ReLU -> hidT
    k_mlpA<<<mlp_grid, 512, A_TOT>>>(pA, pH, W1a, b1a, g1a, be1a, N);
    // (6) MLP1-B: GEMM2 -> h1 (bufB), relu(LN(h1)) (bufC), layer-2 P
    k_mlpB<0><<<mlp_grid, 512, B_TOT>>>(pH, pB, pC, (const float*)0,
                                        W1b, b1b, g_n1, b_n1,
                                        (const float*)0, (const float*)0, pP, t2, N);
    // (7) layer-2 aggregation
    k_agg<<<agg_grid, 256>>>((const float4*)pC, (float4*)pA, pP, pCnt, pAdj, N);
    // (8) MLP2-A
    k_mlpA<<<mlp_grid, 512, A_TOT>>>(pA, pH, W2a, b2a, g2a, be2a, N);
    // (9) MLP2-B + residual + final head -> out
    k_mlpB<1><<<mlp_grid, 512, B_TOT>>>(pH, out, (float*)0, pB,
                                        W2b, b2b, g_n0, b_n0,
                                        W_lin, b_lin, (uint4*)0, (const float*)0, N);
}

// round 14
// speedup vs baseline: 1.0724x; 1.0121x over previous
#include <cuda_runtime.h>
#include <cuda_fp16.h>
#include <cstdint>
#include <math.h>

#define MAXN 100000
#define MAXE 1600000
#define PAD 64
#define TM 128
#define LOG2E 1.44269504088896f

typedef unsigned long long ull;

// ---------------- scratch (static device globals; no allocs) ----------------
__device__ float  d_bufA[MAXN * 64];     // agg output (both layers)
__device__ float  d_bufB[MAXN * 64];     // h1
__device__ float  d_bufC[MAXN * 64];     // relu(LN(h1))
__device__ float  d_bufE[MAXN * 64];     // h0
__device__ uint4  d_P[MAXN * 16];        // per-node (vw,w) half2 pairs
__device__ int    d_cnt[MAXN];
__device__ int    d_adj[MAXN * PAD];
__device__ __half d_hidT[128 * MAXN];    // transposed fp16 hidden [k][n]

// packed fp32x2 helpers (sm_103a FFMA2 path)
#define PK(d, lo, hi)  asm("mov.b64 %0, {%1, %2};" : "=l"(d) : "f"(lo), "f"(hi))
#define UPK(lo, hi, s) asm("mov.b64 {%0, %1}, %2;" : "=f"(lo), "=f"(hi) : "l"(s))
#define FMA2(d, a, b, c) asm("fma.rn.f32x2 %0, %1, %2, %3;" : "=l"(d) : "l"(a), "l"(b), "l"(c))

// ---------------- encoder: h0 + fused P(t1) + zero cnt ----------------------
__global__ void k_encoder(const float* __restrict__ x, const float* __restrict__ W,
                          const float* __restrict__ b, float* __restrict__ h,
                          uint4* __restrict__ P, const float* __restrict__ tptr,
                          int* __restrict__ cnt, int N) {
    __shared__ float4 sW[16 * 16];
    __shared__ float4 sB[16];
    int tid = threadIdx.x;
    if (tid < 256) sW[tid] = ((const float4*)W)[tid];
    if (tid < 16)  sB[tid] = ((const float4*)b)[tid];
    __syncthreads();
    int idx = blockIdx.x * blockDim.x + threadIdx.x;
    if (idx < N) cnt[idx] = 0;
    int total = N * 16;
    if (idx >= total) return;
    int n = idx >> 4, q = idx & 15;
    const float4* xr = (const float4*)(x + n * 16);
    float4 x0 = xr[0], x1 = xr[1], x2 = xr[2], x3 = xr[3];
    float4 acc = sB[q];
    #define ESTEP(xv, kk) { float4 w = sW[(kk) * 16 + q]; \
        acc.x += (xv) * w.x; acc.y += (xv) * w.y; acc.z += (xv) * w.z; acc.w += (xv) * w.w; }
    ESTEP(x0.x, 0)  ESTEP(x0.y, 1)  ESTEP(x0.z, 2)  ESTEP(x0.w, 3)
    ESTEP(x1.x, 4)  ESTEP(x1.y, 5)  ESTEP(x1.z, 6)  ESTEP(x1.w, 7)
    ESTEP(x2.x, 8)  ESTEP(x2.y, 9)  ESTEP(x2.z, 10) ESTEP(x2.w, 11)
    ESTEP(x3.x, 12) ESTEP(x3.y, 13) ESTEP(x3.z, 14) ESTEP(x3.w, 15)
    #undef ESTEP
    ((float4*)h)[idx] = acc;
    // fused layer-1 P precompute: v = relu(h0)+eps, w = exp2(v*t*log2e)
    float c = __ldg(tptr) * LOG2E;
    float vx = fmaxf(acc.x, 0.f) + 1e-7f;
    float vy = fmaxf(acc.y, 0.f) + 1e-7f;
    float vz = fmaxf(acc.z, 0.f) + 1e-7f;
    float vw = fmaxf(acc.w, 0.f) + 1e-7f;
    float wx = exp2f(vx * c), wy = exp2f(vy * c);
    float wz = exp2f(vz * c), ww = exp2f(vw * c);
    __half2 p0 = __floats2half2_rn(vx * wx, wx);
    __half2 p1 = __floats2half2_rn(vy * wy, wy);
    __half2 p2 = __floats2half2_rn(vz * wz, wz);
    __half2 p3 = __floats2half2_rn(vw * ww, ww);
    uint4 u;
    u.x = *(unsigned*)&p0; u.y = *(unsigned*)&p1;
    u.z = *(unsigned*)&p2; u.w = *(unsigned*)&p3;
    P[idx] = u;
}

// ---------------- bucket placement ----------------
__global__ void k_place(const int* __restrict__ src, const int* __restrict__ dst,
                        int* __restrict__ cnt, int* __restrict__ adj, int E) {
    int e = blockIdx.x * blockDim.x + threadIdx.x;
    if (e >= E) return;
    int d = dst[e];
    int p = atomicAdd(&cnt[d], 1);
    if (p < PAD) adj[(d << 6) + p] = src[e];
}

// ---------------- aggregation: fp16 P gather (round-6 best) ----------------
#define ACCP(p) { \
    float2 q0 = __half22float2(*(__half2*)&(p).x); \
    float2 q1 = __half22float2(*(__half2*)&(p).y); \
    float2 q2 = __half22float2(*(__half2*)&(p).z); \
    float2 q3 = __half22float2(*(__half2*)&(p).w); \
    n0 += q0.x; d0 += q0.y; n1 += q1.x; d1 += q1.y; \
    n2 += q2.x; d2 += q2.y; n3 += q3.x; d3 += q3.y; }

__global__ void __launch_bounds__(256)
k_agg(const float4* __restrict__ feat4, float4* __restrict__ out4,
      const uint4* __restrict__ P, const int* __restrict__ cnt,
      const int* __restrict__ adj, int N) {
    int gid = (blockIdx.x * 256 + threadIdx.x) >> 4;
    if (gid >= N) return;
    int f = threadIdx.x & 15;
    int deg = cnt[gid]; deg = min(deg, PAD);
    const int4* lst4 = (const int4*)(adj + (gid << 6));
    float n0 = 0.f, n1 = 0.f, n2 = 0.f, n3 = 0.f;
    float d0 = 0.f, d1 = 0.f, d2 = 0.f, d3 = 0.f;
    int full = deg >> 2;
    for (int c = 0; c < full; c++) {
        int4 s = lst4[c];
        uint4 p0 = P[s.x * 16 + f];
        uint4 p1 = P[s.y * 16 + f];
        uint4 p2 = P[s.z * 16 + f];
        uint4 p3 = P[s.w * 16 + f];
        ACCP(p0); ACCP(p1); ACCP(p2); ACCP(p3);
    }
    int r = deg & 3;
    if (r) {
        int4 s = lst4[full];
        uint4 p0 = P[s.x * 16 + f]; ACCP(p0);
        if (r > 1) { uint4 p1 = P[s.y * 16 + f]; ACCP(p1); }
        if (r > 2) { uint4 p2 = P[s.z * 16 + f]; ACCP(p2); }
    }
    float4 self = feat4[gid * 16 + f];
    float4 o;
    o.x = n0 / (d0 + 1e-16f) + self.x;
    o.y = n1 / (d1 + 1e-16f) + self.y;
    o.z = n2 / (d2 + 1e-16f) + self.z;
    o.w = n3 / (d3 + 1e-16f) + self.w;
    out4[gid * 16 + f] = o;
}

// ---------------- MLP kernel A: GEMM1 + LN128 + ReLU -> hidT fp16 -----------
#define A_W1  0
#define A_IN  8192
#define A_RS  16384
#define A_RQ  18432
#define A_MU  20480
#define A_INV 20608
#define A_B1  20736
#define A_G1  20864
#define A_BE1 20992
#define A_TOT (21120 * 4)

__global__ void __launch_bounds__(512, 2)
k_mlpA(const float* __restrict__ in, __half* __restrict__ hidT,
       const float* __restrict__ W1, const float* __restrict__ b1,
       const float* __restrict__ g1, const float* __restrict__ be1, int N) {
    extern __shared__ float sm[];
    const int tid = threadIdx.x;
    const int mg  = tid & 31;
    const int jg  = tid >> 5;

    {
        const float4* W14 = (const float4*)W1;
        float4* sW14 = (float4*)(sm + A_W1);
        #pragma unroll
        for (int i = 0; i < 4; i++) sW14[tid + i * 512] = W14[tid + i * 512];
        if (tid < 128) {
            sm[A_B1 + tid]  = b1[tid];
            sm[A_G1 + tid]  = g1[tid];
            sm[A_BE1 + tid] = be1[tid];
        }
    }
    {
        int nl = tid & 127;
        int q  = tid >> 7;
        int n  = blockIdx.x * TM + nl;
        if (n >= N) n = N - 1;
        const float4* ip = (const float4*)(in + (size_t)n * 64);
        #pragma unroll
        for (int i = 0; i < 4; i++) {
            float4 v = ip[q * 4 + i];
            int k0 = (q * 4 + i) * 4;
            sm[A_IN + (k0 + 0) * TM + nl] = v.x;
            sm[A_IN + (k0 + 1) * TM + nl] = v.y;
            sm[A_IN + (k0 + 2) * TM + nl] = v.z;
            sm[A_IN + (k0 + 3) * TM + nl] = v.w;
        }
    }
    __syncthreads();

    // GEMM1: [128 x 64] @ [64 x 128]; thread tile 4m x 8j
    ull acc[4][4];
    #pragma unroll
    for (int a = 0; a < 4; a++)
        #pragma unroll
        for (int bq = 0; bq < 4; bq++) acc[a][bq] = 0ull;

    const float4* sIn4 = (const float4*)(sm + A_IN);
    const float4* sW14 = (const float4*)(sm + A_W1);
    #pragma unroll 8
    for (int k = 0; k < 64; k++) {
        float4 a  = sIn4[k * 32 + mg];
        float4 w0 = sW14[k * 32 + (jg << 1)];
        float4 w1 = sW14[k * 32 + (jg << 1) + 1];
        ull pa0, pa1, pa2, pa3, q0, q1, q2, q3;
        PK(pa0, a.x, a.x); PK(pa1, a.y, a.y); PK(pa2, a.z, a.z); PK(pa3, a.w, a.w);
        PK(q0, w0.x, w0.y); PK(q1, w0.z, w0.w); PK(q2, w1.x, w1.y); PK(q3, w1.z, w1.w);
        FMA2(acc[0][0], pa0, q0, acc[0][0]); FMA2(acc[0][1], pa0, q1, acc[0][1]);
        FMA2(acc[0][2], pa0, q2, acc[0][2]); FMA2(acc[0][3], pa0, q3, acc[0][3]);
        FMA2(acc[1][0], pa1, q0, acc[1][0]); FMA2(acc[1][1], pa1, q1, acc[1][1]);
        FMA2(acc[1][2], pa1, q2, acc[1][2]); FMA2(acc[1][3], pa1, q3, acc[1][3]);
        FMA2(acc[2][0], pa2, q0, acc[2][0]); FMA2(acc[2][1], pa2, q1, acc[2][1]);
        FMA2(acc[2][2], pa2, q2, acc[2][2]); FMA2(acc[2][3], pa2, q3, acc[2][3]);
        FMA2(acc[3][0], pa3, q0, acc[3][0]); FMA2(acc[3][1], pa3, q1, acc[3][1]);
        FMA2(acc[3][2], pa3, q2, acc[3][2]); FMA2(acc[3][3], pa3, q3, acc[3][3]);
    }

    // bias + per-node partial LN sums (over 128 hidden)
    float hreg[4][8];
    {
        float4 psum, psq;
        float* ps = (float*)&psum;
        float* pq = (float*)&psq;
        #pragma unroll
        for (int mi = 0; mi < 4; mi++) {
            float s = 0.f, q = 0.f;
            #pragma unroll
            for (int jp = 0; jp < 4; jp++) {
                float lo, hi;
                UPK(lo, hi, acc[mi][jp]);
                lo += sm[A_B1 + (jg << 3) + 2 * jp];
                hi += sm[A_B1 + (jg << 3) + 2 * jp + 1];
                hreg[mi][2 * jp] = lo; hreg[mi][2 * jp + 1] = hi;
                s += lo + hi; q += lo * lo + hi * hi;
            }
            ps[mi] = s; pq[mi] = q;
        }
        *(float4*)&sm[A_RS + jg * TM + (mg << 2)] = psum;
        *(float4*)&sm[A_RQ + jg * TM + (mg << 2)] = psq;
    }
    __syncthreads();
    if (tid < TM) {
        float s = 0.f, q = 0.f;
        #pragma unroll
        for (int g = 0; g < 16; g++) { s += sm[A_RS + g * TM + tid]; q += sm[A_RQ + g * TM + tid]; }
        float mu = s * (1.f / 128.f);
        float var = q * (1.f / 128.f) - mu * mu;
        sm[A_MU + tid]  = mu;
        sm[A_INV + tid] = rsqrtf(var + 1e-5f);
    }
    __syncthreads();

    // LN + ReLU -> fp16, store transposed hidT[j][n]
    {
        float mu[4], iv[4];
        int n0 = blockIdx.x * TM + (mg << 2);
        #pragma unroll
        for (int mi = 0; mi < 4; mi++) {
            mu[mi] = sm[A_MU + (mg << 2) + mi];
            iv[mi] = sm[A_INV + (mg << 2) + mi];
        }
        #pragma unroll
        for (int jj = 0; jj < 8; jj++) {
            int j = (jg << 3) + jj;
            float gg = sm[A_G1 + j], bb = sm[A_BE1 + j];
            float y0 = fmaxf((hreg[0][jj] - mu[0]) * iv[0] * gg + bb, 0.f);
            float y1 = fmaxf((hreg[1][jj] - mu[1]) * iv[1] * gg + bb, 0.f);
            float y2 = fmaxf((hreg[2][jj] - mu[2]) * iv[2] * gg + bb, 0.f);
            float y3 = fmaxf((hreg[3][jj] - mu[3]) * iv[3] * gg + bb, 0.f);
            __half2 hlo = __floats2half2_rn(y0, y1);
            __half2 hhi = __floats2half2_rn(y2, y3);
            __half* dstp = hidT + (size_t)j * MAXN + n0;
            if (n0 + 3 < N) {
                uint2 u;
                u.x = *(unsigned*)&hlo; u.y = *(unsigned*)&hhi;
                *(uint2*)dstp = u;
            } else {
                if (n0 + 0 < N) dstp[0] = __low2half(hlo);
                if (n0 + 1 < N) dstp[1] = __high2half(hlo);
                if (n0 + 2 < N) dstp[2] = __low2half(hhi);
                if (n0 + 3 < N) dstp[3] = __high2half(hhi);
            }
        }
    }
}

// ---------------- MLP kernel B: GEMM2 (hid fp16) + fused epilogue -----------
#define B_W2  0
#define B_HID 8192
#define B_RS  16384
#define B_RQ  18432
#define B_MU  20480
#define B_INV 20608
#define B_B2  20736
#define B_GX  20800
#define B_BX  20864
#define B_WL  20928
#define B_TOT (20992 * 4)

template <int MODE>
__global__ void __launch_bounds__(512, 2)
k_mlpB(const __half* __restrict__ hidT, float* __restrict__ out,
       float* __restrict__ out2, const float* __restrict__ res,
       const float* __restrict__ W2, const float* __restrict__ b2,
       const float* __restrict__ gx, const float* __restrict__ bx,
       const float* __restrict__ Wl, const float* __restrict__ bl,
       uint4* __restrict__ Pout, const float* __restrict__ tp, int N) {
    extern __shared__ float sm[];
    const int tid = threadIdx.x;
    const int mg  = tid & 31;
    const int jg  = tid >> 5;

    {
        const float4* W24 = (const float4*)W2;
        float4* sW24 = (float4*)(sm + B_W2);
        #pragma unroll
        for (int i = 0; i < 4; i++) sW24[tid + i * 512] = W24[tid + i * 512];
        if (tid < 64) {
            sm[B_B2 + tid] = b2[tid];
            sm[B_GX + tid] = gx[tid];
            sm[B_BX + tid] = bx[tid];
            sm[B_WL + tid] = (MODE == 1) ? Wl[tid] : 0.f;
        }
        int kk = tid >> 2;
        int cc = tid & 3;
        const uint4* gh = (const uint4*)(hidT + (size_t)kk * MAXN + blockIdx.x * TM);
        uint4* sh = (uint4*)(sm + B_HID);
        #pragma unroll
        for (int i = 0; i < 4; i++)
            sh[kk * 16 + cc * 4 + i] = gh[cc * 4 + i];
    }
    __syncthreads();

    // GEMM2: [128 x 128(fp16)] @ [128 x 64]; thread tile 4m x 4j
    ull c2[4][2];
    #pragma unroll
    for (int a = 0; a < 4; a++) { c2[a][0] = 0ull; c2[a][1] = 0ull; }

    const float4* sW24 = (const float4*)(sm + B_W2);
    const __half2* sh2 = (const __half2*)(sm + B_HID);
    #pragma unroll 8
    for (int k = 0; k < 128; k++) {
        __half2 ha = sh2[k * 64 + (mg << 1)];
        __half2 hb = sh2[k * 64 + (mg << 1) + 1];
        float2 fa = __half22float2(ha);
        float2 fb = __half22float2(hb);
        float4 w = sW24[(k << 4) + jg];
        ull pa0, pa1, pa2, pa3, q0, q1;
        PK(pa0, fa.x, fa.x); PK(pa1, fa.y, fa.y);
        PK(pa2, fb.x, fb.x); PK(pa3, fb.y, fb.y);
        PK(q0, w.x, w.y); PK(q1, w.z, w.w);
        FMA2(c2[0][0], pa0, q0, c2[0][0]); FMA2(c2[0][1], pa0, q1, c2[0][1]);
        FMA2(c2[1][0], pa1, q0, c2[1][0]); FMA2(c2[1][1], pa1, q1, c2[1][1]);
        FMA2(c2[2][0], pa2, q0, c2[2][0]); FMA2(c2[2][1], pa2, q1, c2[2][1]);
        FMA2(c2[3][0], pa3, q0, c2[3][0]); FMA2(c2[3][1], pa3, q1, c2[3][1]);
    }

    // epilogue: bias (+res), LN64 stats
    const int j0 = jg << 2;
    float o[4][4];
    {
        float b0 = sm[B_B2 + j0],     bb1 = sm[B_B2 + j0 + 1];
        float bb2 = sm[B_B2 + j0 + 2], bb3 = sm[B_B2 + j0 + 3];
        float4 psum, psq;
        float* ps = (float*)&psum;
        float* pq = (float*)&psq;
        #pragma unroll
        for (int mi = 0; mi < 4; mi++) {
            int n = blockIdx.x * TM + (mg << 2) + mi;
            UPK(o[mi][0], o[mi][1], c2[mi][0]);
            UPK(o[mi][2], o[mi][3], c2[mi][1]);
            o[mi][0] += b0; o[mi][1] += bb1; o[mi][2] += bb2; o[mi][3] += bb3;
            if (MODE == 1) {
                int nc = (n < N) ? n : (N - 1);
                float4 r = *(const float4*)&res[(size_t)nc * 64 + j0];
                o[mi][0] += r.x; o[mi][1] += r.y; o[mi][2] += r.z; o[mi][3] += r.w;
            } else {
                if (n < N)
                    *(float4*)&out[(size_t)n * 64 + j0] =
                        make_float4(o[mi][0], o[mi][1], o[mi][2], o[mi][3]);
            }
            float s = (o[mi][0] + o[mi][1]) + (o[mi][2] + o[mi][3]);
            float q = (o[mi][0] * o[mi][0] + o[mi][1] * o[mi][1])
                    + (o[mi][2] * o[mi][2] + o[mi][3] * o[mi][3]);
            ps[mi] = s; pq[mi] = q;
        }
        *(float4*)&sm[B_RS + jg * TM + (mg << 2)] = psum;
        *(float4*)&sm[B_RQ + jg * TM + (mg << 2)] = psq;
    }
    __syncthreads();
    if (tid < TM) {
        float s = 0.f, q = 0.f;
        #pragma unroll
        for (int g = 0; g < 16; g++) { s += sm[B_RS + g * TM + tid]; q += sm[B_RQ + g * TM + tid]; }
        float mu = s * (1.f / 64.f);
        float var = q * (1.f / 64.f) - mu * mu;
        sm[B_MU + tid]  = mu;
        sm[B_INV + tid] = rsqrtf(var + 1e-5f);
    }
    __syncthreads();

    if (MODE == 0) {
        float cP = __ldg(tp) * LOG2E;
        float g0 = sm[B_GX + j0],     g1v = sm[B_GX + j0 + 1];
        float g2v = sm[B_GX + j0 + 2], g3v = sm[B_GX + j0 + 3];
        float x0 = sm[B_BX + j0],     x1 = sm[B_BX + j0 + 1];
        float x2 = sm[B_BX + j0 + 2], x3 = sm[B_BX + j0 + 3];
        #pragma unroll
        for (int mi = 0; mi < 4; mi++) {
            int n = blockIdx.x * TM + (mg << 2) + mi;
            if (n < N) {
                float mu = sm[B_MU + (mg << 2) + mi], iv = sm[B_INV + (mg << 2) + mi];
                float4 y;
                y.x = fmaxf((o[mi][0] - mu) * iv * g0 + x0, 0.f);
                y.y = fmaxf((o[mi][1] - mu) * iv * g1v + x1, 0.f);
                y.z = fmaxf((o[mi][2] - mu) * iv * g2v + x2, 0.f);
                y.w = fmaxf((o[mi][3] - mu) * iv * g3v + x3, 0.f);
                *(float4*)&out2[(size_t)n * 64 + j0] = y;
                float vx = y.x + 1e-7f, vy = y.y + 1e-7f;
                float vz = y.z + 1e-7f, vw = y.w + 1e-7f;
                float wx = exp2f(vx * cP), wy = exp2f(vy * cP);
                float wz = exp2f(vz * cP), ww = exp2f(vw * cP);
                __half2 a0 = __floats2half2_rn(vx * wx, wx);
                __half2 a1 = __floats2half2_rn(vy * wy, wy);
                __half2 a2 = __floats2half2_rn(vz * wz, wz);
                __half2 a3 = __floats2half2_rn(vw * ww, ww);
                uint4 u;
                u.x = *(unsigned*)&a0; u.y = *(unsigned*)&a1;
                u.z = *(unsigned*)&a2; u.w = *(unsigned*)&a3;
                Pout[(size_t)n * 16 + jg] = u;
            }
        }
    } else {
        float g0 = sm[B_GX + j0],     g1v = sm[B_GX + j0 + 1];
        float g2v = sm[B_GX + j0 + 2], g3v = sm[B_GX + j0 + 3];
        float x0 = sm[B_BX + j0],     x1 = sm[B_BX + j0 + 1];
        float x2 = sm[B_BX + j0 + 2], x3 = sm[B_BX + j0 + 3];
        float w0 = sm[B_WL + j0],     w1 = sm[B_WL + j0 + 1];
        float w2 = sm[B_WL + j0 + 2], w3 = sm[B_WL + j0 + 3];
        float4 pdot;
        float* pd = (float*)&pdot;
        #pragma unroll
        for (int mi = 0; mi < 4; mi++) {
            float mu = sm[B_MU + (mg << 2) + mi], iv = sm[B_INV + (mg << 2) + mi];
            float y0 = fmaxf((o[mi][0] - mu) * iv * g0 + x0, 0.f);
            float y1 = fmaxf((o[mi][1] - mu) * iv * g1v + x1, 0.f);
            float y2 = fmaxf((o[mi][2] - mu) * iv * g2v + x2, 0.f);
            float y3 = fmaxf((o[mi][3] - mu) * iv * g3v + x3, 0.f);
            pd[mi] = (y0 * w0 + y1 * w1) + (y2 * w2 + y3 * w3);
        }
        *(float4*)&sm[B_RS + jg * TM + (mg << 2)] = pdot;
        __syncthreads();
        if (tid < TM) {
            int n = blockIdx.x * TM + tid;
            if (n < N) {
                float p = 0.f;
                #pragma unroll
                for (int g = 0; g < 16; g++) p += sm[B_RS + g * TM + tid];
                float logit = p + __ldg(bl);
                out[n]     = 1.f / (1.f + expf(-logit));
                out[N + n] = logit;
            }
        }
    }
}

// ---------------- host launcher ----------------
extern "C" void kernel_launch(void* const* d_in, const int* in_sizes, int n_in,
                              void* d_out, int out_size) {
    const float* x      = (const float*)d_in[0];
    const int*   eidx   = (const int*)d_in[1];
    const float* W_enc  = (const float*)d_in[2];
    const float* b_enc  = (const float*)d_in[3];
    const float* t1     = (const float*)d_in[4];
    const float* W1a    = (const float*)d_in[5];
    const float* b1a    = (const float*)d_in[6];
    const float* g1a    = (const float*)d_in[7];
    const float* be1a   = (const float*)d_in[8];
    const float* W1b    = (const float*)d_in[9];
    const float* b1b    = (const float*)d_in[10];
    const float* g_n1   = (const float*)d_in[11];
    const float* b_n1   = (const float*)d_in[12];
    const float* t2     = (const float*)d_in[13];
    const float* W2a    = (const float*)d_in[14];
    const float* b2a    = (const float*)d_in[15];
    const float* g2a    = (const float*)d_in[16];
    const float* be2a   = (const float*)d_in[17];
    const float* W2b    = (const float*)d_in[18];
    const float* b2b    = (const float*)d_in[19];
    const float* g_n0   = (const float*)d_in[20];
    const float* b_n0   = (const float*)d_in[21];
    const float* W_lin  = (const float*)d_in[22];
    const float* b_lin  = (const float*)d_in[23];
    float* out = (float*)d_out;

    int N = in_sizes[0] / 16;
    int E = in_sizes[1] / 2;
    if (N > MAXN) N = MAXN;
    if (E > MAXE) E = MAXE;
    const int* src = eidx;
    const int* dst = eidx + E;

    float *pA, *pB, *pC, *pE;
    uint4* pP;
    __half* pH;
    int *pCnt, *pAdj;
    cudaGetSymbolAddress((void**)&pA, d_bufA);
    cudaGetSymbolAddress((void**)&pB, d_bufB);
    cudaGetSymbolAddress((void**)&pC, d_bufC);
    cudaGetSymbolAddress((void**)&pE, d_bufE);
    cudaGetSymbolAddress((void**)&pP, d_P);
    cudaGetSymbolAddress((void**)&pH, d_hidT);
    cudaGetSymbolAddress((void**)&pCnt, d_cnt);
    cudaGetSymbolAddress((void**)&pAdj, d_adj);

    cudaFuncSetAttribute(k_mlpA, cudaFuncAttributeMaxDynamicSharedMemorySize, A_TOT);
    cudaFuncSetAttribute(k_mlpB<0>, cudaFuncAttributeMaxDynamicSharedMemorySize, B_TOT);
    cudaFuncSetAttribute(k_mlpB<1>, cudaFuncAttributeMaxDynamicSharedMemorySize, B_TOT);

    int mlp_grid = (N + TM - 1) / TM;
    int agg_grid = (N * 16 + 255) / 256;

    // (1) encoder -> h0 + layer-1 P + zero cnt
    k_encoder<<<(N * 16 + 255) / 256, 256>>>(x, W_enc, b_enc, pE, pP, t1, pCnt, N);
    // (2) bucket placement
    k_place<<<(E + 255) / 256, 256>>>(src, dst, pCnt, pAdj, E);
    // (3) layer-1 aggregation
    k_agg<<<agg_grid, 256>>>((const float4*)pE, (float4*)pA, pP, pCnt, pAdj, N);
    // (4) MLP1-A: GEMM1 + LN + ReLU -> hidT   [profiled slot]
    k_mlpA<<<mlp_grid, 512, A_TOT>>>(pA, pH, W1a, b1a, g1a, be1a, N);
    // (5) MLP1-B: GEMM2 -> h1 (bufB), relu(LN(h1)) (bufC), layer-2 P
    k_mlpB<0><<<mlp_grid, 512, B_TOT>>>(pH, pB, pC, (const float*)0,
                                        W1b, b1b, g_n1, b_n1,
                                        (const float*)0, (const float*)0, pP, t2, N);
    // (6) layer-2 aggregation
    k_agg<<<agg_grid, 256>>>((const float4*)pC, (float4*)pA, pP, pCnt, pAdj, N);
    // (7) MLP2-A
    k_mlpA<<<mlp_grid, 512, A_TOT>>>(pA, pH, W2a, b2a, g2a, be2a, N);
    // (8) MLP2-B + residual + final head -> out
    k_mlpB<1><<<mlp_grid, 512, B_TOT>>>(pH, out, (float*)0, pB,
                                        W2b, b2b, g_n0, b_n0,
                                        W_lin, b_lin, (uint4*)0, (const float*)0, N);
}

// round 15
// speedup vs baseline: 1.4705x; 1.3712x over previous
#include <cuda_runtime.h>
#include <cuda_fp16.h>
#include <cstdint>
#include <math.h>

#define MAXN 100000
#define MAXE 1600000
#define PAD 64
#define LOG2E 1.44269504088896f

typedef unsigned long long ull;

// ---------------- scratch (static device globals; no allocs) ----------------
__device__ float  d_bufA[MAXN * 64];     // agg output (both layers)
__device__ float  d_bufB[MAXN * 64];     // h1
__device__ float  d_bufC[MAXN * 64];     // relu(LN(h1))
__device__ float  d_bufE[MAXN * 64];     // h0
__device__ uint4  d_P[MAXN * 16];        // per-node (vw,w) half2 pairs
__device__ int    d_cnt[MAXN];
__device__ int    d_adj[MAXN * PAD];
__device__ __half d_hidG[(size_t)MAXN * 128];  // hidden fp16 [node][128]
// fp16 transposed weights [j][k]
__device__ __half d_W1aT[8192], d_W1bT[8192], d_W2aT[8192], d_W2bT[8192];

// ---------------- mma.sync m16n8k16 (HMMA fallback path) --------------------
__device__ __forceinline__ void mma16816(float& c0, float& c1, float& c2, float& c3,
                                         uint32_t a0, uint32_t a1, uint32_t a2,
                                         uint32_t a3, uint32_t b0, uint32_t b1) {
    asm volatile("mma.sync.aligned.m16n8k16.row.col.f32.f16.f16.f32 "
                 "{%0,%1,%2,%3}, {%4,%5,%6,%7}, {%8,%9}, {%0,%1,%2,%3};"
                 : "+f"(c0), "+f"(c1), "+f"(c2), "+f"(c3)
                 : "r"(a0), "r"(a1), "r"(a2), "r"(a3), "r"(b0), "r"(b1));
}

// ---------------- encoder: h0 + P(t1) + zero cnt + fp16 weight transpose ----
__global__ void k_encoder(const float* __restrict__ x, const float* __restrict__ W,
                          const float* __restrict__ b, float* __restrict__ h,
                          uint4* __restrict__ P, const float* __restrict__ tptr,
                          int* __restrict__ cnt, int N,
                          const float* __restrict__ Wa1, const float* __restrict__ Wb1,
                          const float* __restrict__ Wa2, const float* __restrict__ Wb2,
                          __half* __restrict__ T1a, __half* __restrict__ T1b,
                          __half* __restrict__ T2a, __half* __restrict__ T2b) {
    __shared__ float4 sW[16 * 16];
    __shared__ float4 sB[16];
    int tid = threadIdx.x;
    if (tid < 256) sW[tid] = ((const float4*)W)[tid];
    if (tid < 16)  sB[tid] = ((const float4*)b)[tid];
    __syncthreads();
    int idx = blockIdx.x * blockDim.x + threadIdx.x;
    if (idx < N) cnt[idx] = 0;

    if (idx < 8192) {            // GEMM1 weights [64 k][128 j] -> T[j][k]
        int j = idx >> 6, k = idx & 63;
        T1a[j * 64 + k] = __float2half_rn(Wa1[k * 128 + j]);
        T2a[j * 64 + k] = __float2half_rn(Wa2[k * 128 + j]);
    } else if (idx < 16384) {    // GEMM2 weights [128 k][64 j] -> T[j][k]
        int i = idx - 8192;
        int j = i >> 7, k = i & 127;
        T1b[j * 128 + k] = __float2half_rn(Wb1[k * 64 + j]);
        T2b[j * 128 + k] = __float2half_rn(Wb2[k * 64 + j]);
    }

    int total = N * 16;
    if (idx >= total) return;
    int n = idx >> 4, q = idx & 15;
    const float4* xr = (const float4*)(x + n * 16);
    float4 x0 = xr[0], x1 = xr[1], x2 = xr[2], x3 = xr[3];
    float4 acc = sB[q];
    #define ESTEP(xv, kk) { float4 w = sW[(kk) * 16 + q]; \
        acc.x += (xv) * w.x; acc.y += (xv) * w.y; acc.z += (xv) * w.z; acc.w += (xv) * w.w; }
    ESTEP(x0.x, 0)  ESTEP(x0.y, 1)  ESTEP(x0.z, 2)  ESTEP(x0.w, 3)
    ESTEP(x1.x, 4)  ESTEP(x1.y, 5)  ESTEP(x1.z, 6)  ESTEP(x1.w, 7)
    ESTEP(x2.x, 8)  ESTEP(x2.y, 9)  ESTEP(x2.z, 10) ESTEP(x2.w, 11)
    ESTEP(x3.x, 12) ESTEP(x3.y, 13) ESTEP(x3.z, 14) ESTEP(x3.w, 15)
    #undef ESTEP
    ((float4*)h)[idx] = acc;
    float c = __ldg(tptr) * LOG2E;
    float vx = fmaxf(acc.x, 0.f) + 1e-7f;
    float vy = fmaxf(acc.y, 0.f) + 1e-7f;
    float vz = fmaxf(acc.z, 0.f) + 1e-7f;
    float vw = fmaxf(acc.w, 0.f) + 1e-7f;
    float wx = exp2f(vx * c), wy = exp2f(vy * c);
    float wz = exp2f(vz * c), ww = exp2f(vw * c);
    __half2 p0 = __floats2half2_rn(vx * wx, wx);
    __half2 p1 = __floats2half2_rn(vy * wy, wy);
    __half2 p2 = __floats2half2_rn(vz * wz, wz);
    __half2 p3 = __floats2half2_rn(vw * ww, ww);
    uint4 u;
    u.x = *(unsigned*)&p0; u.y = *(unsigned*)&p1;
    u.z = *(unsigned*)&p2; u.w = *(unsigned*)&p3;
    P[idx] = u;
}

// ---------------- bucket placement ----------------
__global__ void k_place(const int* __restrict__ src, const int* __restrict__ dst,
                        int* __restrict__ cnt, int* __restrict__ adj, int E) {
    int e = blockIdx.x * blockDim.x + threadIdx.x;
    if (e >= E) return;
    int d = dst[e];
    int p = atomicAdd(&cnt[d], 1);
    if (p < PAD) adj[(d << 6) + p] = src[e];
}

// ---------------- aggregation: fp16 P gather (round-6 best) ----------------
#define ACCP(p) { \
    float2 q0 = __half22float2(*(__half2*)&(p).x); \
    float2 q1 = __half22float2(*(__half2*)&(p).y); \
    float2 q2 = __half22float2(*(__half2*)&(p).z); \
    float2 q3 = __half22float2(*(__half2*)&(p).w); \
    n0 += q0.x; d0 += q0.y; n1 += q1.x; d1 += q1.y; \
    n2 += q2.x; d2 += q2.y; n3 += q3.x; d3 += q3.y; }

__global__ void __launch_bounds__(256)
k_agg(const float4* __restrict__ feat4, float4* __restrict__ out4,
      const uint4* __restrict__ P, const int* __restrict__ cnt,
      const int* __restrict__ adj, int N) {
    int gid = (blockIdx.x * 256 + threadIdx.x) >> 4;
    if (gid >= N) return;
    int f = threadIdx.x & 15;
    int deg = cnt[gid]; deg = min(deg, PAD);
    const int4* lst4 = (const int4*)(adj + (gid << 6));
    float n0 = 0.f, n1 = 0.f, n2 = 0.f, n3 = 0.f;
    float d0 = 0.f, d1 = 0.f, d2 = 0.f, d3 = 0.f;
    int full = deg >> 2;
    for (int c = 0; c < full; c++) {
        int4 s = lst4[c];
        uint4 p0 = P[s.x * 16 + f];
        uint4 p1 = P[s.y * 16 + f];
        uint4 p2 = P[s.z * 16 + f];
        uint4 p3 = P[s.w * 16 + f];
        ACCP(p0); ACCP(p1); ACCP(p2); ACCP(p3);
    }
    int r = deg & 3;
    if (r) {
        int4 s = lst4[full];
        uint4 p0 = P[s.x * 16 + f]; ACCP(p0);
        if (r > 1) { uint4 p1 = P[s.y * 16 + f]; ACCP(p1); }
        if (r > 2) { uint4 p2 = P[s.z * 16 + f]; ACCP(p2); }
    }
    float4 self = feat4[gid * 16 + f];
    float4 o;
    o.x = n0 / (d0 + 1e-16f) + self.x;
    o.y = n1 / (d1 + 1e-16f) + self.y;
    o.z = n2 / (d2 + 1e-16f) + self.z;
    o.w = n3 / (d3 + 1e-16f) + self.w;
    out4[gid * 16 + f] = o;
}

// ---------------- MLP-A (HMMA): GEMM1[128x128x64] + LN128 + ReLU -> hidG ----
// smem halves: sA [128][136], sW [128][136]; params: b1,g1,be1 float[128]
#define MA_W   (128 * 136)
#define MA_PARB (2 * 136 * 256)           // byte offset of params
#define MA_TOT (MA_PARB + 3 * 128 * 4)

__global__ void __launch_bounds__(256)
k_mlpA(const float* __restrict__ in, __half* __restrict__ hidG,
       const __half* __restrict__ WT, const float* __restrict__ b1,
       const float* __restrict__ g1, const float* __restrict__ be1, int N) {
    extern __shared__ char smc[];
    __half* smh = (__half*)smc;
    float* pb = (float*)(smc + MA_PARB);
    float* pg = pb + 128;
    float* pe = pg + 128;
    const int tid = threadIdx.x;

    // load input tile (fp32 -> fp16) [128][136]
    {
        int row = tid >> 1, seg = tid & 1;
        int n = blockIdx.x * 128 + row;
        int nc = (n < N) ? n : (N - 1);
        const float4* ip = (const float4*)(in + (size_t)nc * 64);
        #pragma unroll
        for (int i = 0; i < 8; i++) {
            float4 v = ip[seg * 8 + i];
            __half2 ha = __floats2half2_rn(v.x, v.y);
            __half2 hb = __floats2half2_rn(v.z, v.w);
            uint2 u;
            u.x = *(unsigned*)&ha; u.y = *(unsigned*)&hb;
            *(uint2*)(smh + row * 136 + seg * 32 + i * 4) = u;
        }
        // weights [128][64] -> [128][136]
        const uint4* wg = (const uint4*)WT;
        #pragma unroll
        for (int i = 0; i < 4; i++)
            *(uint4*)(smh + MA_W + row * 136 + seg * 32 + i * 8) =
                wg[row * 8 + seg * 4 + i];
        if (tid < 128) { pb[tid] = b1[tid]; pg[tid] = g1[tid]; pe[tid] = be1[tid]; }
    }
    __syncthreads();

    const int lane = tid & 31, w = tid >> 5;
    const int gid = lane >> 2, tig = lane & 3;
    const int m0 = w * 16;
    float acc[64];
    #pragma unroll
    for (int i = 0; i < 64; i++) acc[i] = 0.f;

    const __half* Ab = smh + (m0 + gid) * 136 + tig * 2;
    #pragma unroll
    for (int ks = 0; ks < 4; ks++) {
        int k0 = ks * 16;
        uint32_t a0 = *(const uint32_t*)(Ab + k0);
        uint32_t a1 = *(const uint32_t*)(Ab + 8 * 136 + k0);
        uint32_t a2 = *(const uint32_t*)(Ab + k0 + 8);
        uint32_t a3 = *(const uint32_t*)(Ab + 8 * 136 + k0 + 8);
        #pragma unroll
        for (int nt = 0; nt < 16; nt++) {
            const __half* Bb = smh + MA_W + (nt * 8 + gid) * 136 + tig * 2 + k0;
            uint32_t b0 = *(const uint32_t*)(Bb);
            uint32_t b1r = *(const uint32_t*)(Bb + 8);
            mma16816(acc[nt*4+0], acc[nt*4+1], acc[nt*4+2], acc[nt*4+3],
                     a0, a1, a2, a3, b0, b1r);
        }
    }

    // bias + LN stats (rows m0+gid and m0+gid+8; cols j0 = nt*8+tig*2,+1)
    float s0 = 0.f, q0 = 0.f, s1 = 0.f, q1 = 0.f;
    #pragma unroll
    for (int nt = 0; nt < 16; nt++) {
        int j0 = nt * 8 + tig * 2;
        float2 bb = *(float2*)&pb[j0];
        float v0 = acc[nt*4+0] + bb.x, v1 = acc[nt*4+1] + bb.y;
        float v2 = acc[nt*4+2] + bb.x, v3 = acc[nt*4+3] + bb.y;
        acc[nt*4+0] = v0; acc[nt*4+1] = v1; acc[nt*4+2] = v2; acc[nt*4+3] = v3;
        s0 += v0 + v1; q0 += v0*v0 + v1*v1;
        s1 += v2 + v3; q1 += v2*v2 + v3*v3;
    }
    s0 += __shfl_xor_sync(0xffffffffu, s0, 1); s0 += __shfl_xor_sync(0xffffffffu, s0, 2);
    q0 += __shfl_xor_sync(0xffffffffu, q0, 1); q0 += __shfl_xor_sync(0xffffffffu, q0, 2);
    s1 += __shfl_xor_sync(0xffffffffu, s1, 1); s1 += __shfl_xor_sync(0xffffffffu, s1, 2);
    q1 += __shfl_xor_sync(0xffffffffu, q1, 1); q1 += __shfl_xor_sync(0xffffffffu, q1, 2);
    float mu0 = s0 * (1.f / 128.f), iv0 = rsqrtf(q0 * (1.f / 128.f) - mu0 * mu0 + 1e-5f);
    float mu1 = s1 * (1.f / 128.f), iv1 = rsqrtf(q1 * (1.f / 128.f) - mu1 * mu1 + 1e-5f);

    // LN + ReLU -> fp16 into sA region (reused as hid [128][136]); own rows only
    #pragma unroll
    for (int nt = 0; nt < 16; nt++) {
        int j0 = nt * 8 + tig * 2;
        float2 gg = *(float2*)&pg[j0];
        float2 ee = *(float2*)&pe[j0];
        float y00 = fmaxf((acc[nt*4+0] - mu0) * iv0 * gg.x + ee.x, 0.f);
        float y01 = fmaxf((acc[nt*4+1] - mu0) * iv0 * gg.y + ee.y, 0.f);
        float y10 = fmaxf((acc[nt*4+2] - mu1) * iv1 * gg.x + ee.x, 0.f);
        float y11 = fmaxf((acc[nt*4+3] - mu1) * iv1 * gg.y + ee.y, 0.f);
        __half2 h0 = __floats2half2_rn(y00, y01);
        __half2 h1v = __floats2half2_rn(y10, y11);
        *(uint32_t*)(smh + (m0 + gid) * 136 + j0)     = *(unsigned*)&h0;
        *(uint32_t*)(smh + (m0 + gid + 8) * 136 + j0) = *(unsigned*)&h1v;
    }
    __syncthreads();

    // copy hid smem -> global [node][128] (coalesced)
    {
        int row = tid >> 1, seg = tid & 1;
        uint4* gp = (uint4*)hidG;
        size_t base = ((size_t)(blockIdx.x * 128 + row)) * 16 + seg * 8;
        #pragma unroll
        for (int i = 0; i < 8; i++)
            gp[base + i] = *(uint4*)(smh + row * 136 + seg * 64 + i * 8);
    }
}

// ---------------- MLP-B (HMMA): GEMM2[128x64x128] + fused epilogue ----------
// smem halves: sH [128][136], sW2 [64][136]; params: b2,gx,bx,wl float[64]
#define MB_W   (128 * 136)
#define MB_PARB (2 * 136 * 192)
#define MB_TOT (MB_PARB + 4 * 64 * 4)

template <int MODE>
__global__ void __launch_bounds__(256)
k_mlpB(const __half* __restrict__ hidG, float* __restrict__ out,
       float* __restrict__ out2, const float* __restrict__ res,
       const __half* __restrict__ WT, const float* __restrict__ b2,
       const float* __restrict__ gx, const float* __restrict__ bx,
       const float* __restrict__ Wl, const float* __restrict__ bl,
       uint4* __restrict__ Pout, const float* __restrict__ tp, int N) {
    extern __shared__ char smc[];
    __half* smh = (__half*)smc;
    float* pb = (float*)(smc + MB_PARB);
    float* pg = pb + 64;
    float* px = pg + 64;
    float* pw = px + 64;
    const int tid = threadIdx.x;

    {
        int row = tid >> 1, seg = tid & 1;     // hid rows
        const uint4* gp = (const uint4*)hidG;
        size_t base = ((size_t)(blockIdx.x * 128 + row)) * 16 + seg * 8;
        #pragma unroll
        for (int i = 0; i < 8; i++)
            *(uint4*)(smh + row * 136 + seg * 64 + i * 8) = gp[base + i];
        int r3 = tid >> 2, s3 = tid & 3;       // W2T [64][128]
        const uint4* wg = (const uint4*)WT;
        #pragma unroll
        for (int i = 0; i < 4; i++)
            *(uint4*)(smh + MB_W + r3 * 136 + s3 * 32 + i * 8) =
                wg[r3 * 16 + s3 * 4 + i];
        if (tid < 64) {
            pb[tid] = b2[tid]; pg[tid] = gx[tid]; px[tid] = bx[tid];
            pw[tid] = (MODE == 1) ? Wl[tid] : 0.f;
        }
    }
    __syncthreads();

    const int lane = tid & 31, w = tid >> 5;
    const int gid = lane >> 2, tig = lane & 3;
    const int m0 = w * 16;
    float acc[32];
    #pragma unroll
    for (int i = 0; i < 32; i++) acc[i] = 0.f;

    const __half* Ab = smh + (m0 + gid) * 136 + tig * 2;
    #pragma unroll
    for (int ks = 0; ks < 8; ks++) {
        int k0 = ks * 16;
        uint32_t a0 = *(const uint32_t*)(Ab + k0);
        uint32_t a1 = *(const uint32_t*)(Ab + 8 * 136 + k0);
        uint32_t a2 = *(const uint32_t*)(Ab + k0 + 8);
        uint32_t a3 = *(const uint32_t*)(Ab + 8 * 136 + k0 + 8);
        #pragma unroll
        for (int nt = 0; nt < 8; nt++) {
            const __half* Bb = smh + MB_W + (nt * 8 + gid) * 136 + tig * 2 + k0;
            uint32_t b0 = *(const uint32_t*)(Bb);
            uint32_t b1r = *(const uint32_t*)(Bb + 8);
            mma16816(acc[nt*4+0], acc[nt*4+1], acc[nt*4+2], acc[nt*4+3],
                     a0, a1, a2, a3, b0, b1r);
        }
    }

    const int node0 = blockIdx.x * 128 + m0 + gid;
    const int node1 = node0 + 8;
    const int nc0 = (node0 < N) ? node0 : (N - 1);
    const int nc1 = (node1 < N) ? node1 : (N - 1);

    // bias (+res), h1 store (MODE 0), LN64 stats
    float s0 = 0.f, q0 = 0.f, s1 = 0.f, q1 = 0.f;
    #pragma unroll
    for (int nt = 0; nt < 8; nt++) {
        int j0 = nt * 8 + tig * 2;
        float2 bb = *(float2*)&pb[j0];
        float v0 = acc[nt*4+0] + bb.x, v1 = acc[nt*4+1] + bb.y;
        float v2 = acc[nt*4+2] + bb.x, v3 = acc[nt*4+3] + bb.y;
        if (MODE == 1) {
            float2 r0 = *(const float2*)(res + (size_t)nc0 * 64 + j0);
            float2 r1 = *(const float2*)(res + (size_t)nc1 * 64 + j0);
            v0 += r0.x; v1 += r0.y; v2 += r1.x; v3 += r1.y;
        } else {
            if (node0 < N) *(float2*)(out + (size_t)node0 * 64 + j0) = make_float2(v0, v1);
            if (node1 < N) *(float2*)(out + (size_t)node1 * 64 + j0) = make_float2(v2, v3);
        }
        acc[nt*4+0] = v0; acc[nt*4+1] = v1; acc[nt*4+2] = v2; acc[nt*4+3] = v3;
        s0 += v0 + v1; q0 += v0*v0 + v1*v1;
        s1 += v2 + v3; q1 += v2*v2 + v3*v3;
    }
    s0 += __shfl_xor_sync(0xffffffffu, s0, 1); s0 += __shfl_xor_sync(0xffffffffu, s0, 2);
    q0 += __shfl_xor_sync(0xffffffffu, q0, 1); q0 += __shfl_xor_sync(0xffffffffu, q0, 2);
    s1 += __shfl_xor_sync(0xffffffffu, s1, 1); s1 += __shfl_xor_sync(0xffffffffu, s1, 2);
    q1 += __shfl_xor_sync(0xffffffffu, q1, 1); q1 += __shfl_xor_sync(0xffffffffu, q1, 2);
    float mu0 = s0 * (1.f / 64.f), iv0 = rsqrtf(q0 * (1.f / 64.f) - mu0 * mu0 + 1e-5f);
    float mu1 = s1 * (1.f / 64.f), iv1 = rsqrtf(q1 * (1.f / 64.f) - mu1 * mu1 + 1e-5f);

    if (MODE == 0) {
        float cP = __ldg(tp) * LOG2E;
        unsigned* P32 = (unsigned*)Pout;
        #pragma unroll
        for (int nt = 0; nt < 8; nt++) {
            int j0 = nt * 8 + tig * 2;
            float2 gg = *(float2*)&pg[j0];
            float2 ee = *(float2*)&px[j0];
            float y00 = fmaxf((acc[nt*4+0] - mu0) * iv0 * gg.x + ee.x, 0.f);
            float y01 = fmaxf((acc[nt*4+1] - mu0) * iv0 * gg.y + ee.y, 0.f);
            float y10 = fmaxf((acc[nt*4+2] - mu1) * iv1 * gg.x + ee.x, 0.f);
            float y11 = fmaxf((acc[nt*4+3] - mu1) * iv1 * gg.y + ee.y, 0.f);
            if (node0 < N) {
                *(float2*)(out2 + (size_t)node0 * 64 + j0) = make_float2(y00, y01);
                float va = y00 + 1e-7f, vb = y01 + 1e-7f;
                float wa = exp2f(va * cP), wb = exp2f(vb * cP);
                __half2 pa = __floats2half2_rn(va * wa, wa);
                __half2 pbh = __floats2half2_rn(vb * wb, wb);
                P32[(size_t)node0 * 64 + j0]     = *(unsigned*)&pa;
                P32[(size_t)node0 * 64 + j0 + 1] = *(unsigned*)&pbh;
            }
            if (node1 < N) {
                *(float2*)(out2 + (size_t)node1 * 64 + j0) = make_float2(y10, y11);
                float va = y10 + 1e-7f, vb = y11 + 1e-7f;
                float wa = exp2f(va * cP), wb = exp2f(vb * cP);
                __half2 pa = __floats2half2_rn(va * wa, wa);
                __half2 pbh = __floats2half2_rn(vb * wb, wb);
                P32[(size_t)node1 * 64 + j0]     = *(unsigned*)&pa;
                P32[(size_t)node1 * 64 + j0 + 1] = *(unsigned*)&pbh;
            }
        }
    } else {
        float d0 = 0.f, d1 = 0.f;
        #pragma unroll
        for (int nt = 0; nt < 8; nt++) {
            int j0 = nt * 8 + tig * 2;
            float2 gg = *(float2*)&pg[j0];
            float2 ee = *(float2*)&px[j0];
            float2 wl = *(float2*)&pw[j0];
            float y00 = fmaxf((acc[nt*4+0] - mu0) * iv0 * gg.x + ee.x, 0.f);
            float y01 = fmaxf((acc[nt*4+1] - mu0) * iv0 * gg.y + ee.y, 0.f);
            float y10 = fmaxf((acc[nt*4+2] - mu1) * iv1 * gg.x + ee.x, 0.f);
            float y11 = fmaxf((acc[nt*4+3] - mu1) * iv1 * gg.y + ee.y, 0.f);
            d0 += y00 * wl.x + y01 * wl.y;
            d1 += y10 * wl.x + y11 * wl.y;
        }
        d0 += __shfl_xor_sync(0xffffffffu, d0, 1); d0 += __shfl_xor_sync(0xffffffffu, d0, 2);
        d1 += __shfl_xor_sync(0xffffffffu, d1, 1); d1 += __shfl_xor_sync(0xffffffffu, d1, 2);
        if (tig == 0) {
            float blv = __ldg(bl);
            if (node0 < N) {
                float logit = d0 + blv;
                out[node0]     = 1.f / (1.f + expf(-logit));
                out[N + node0] = logit;
            }
            if (node1 < N) {
                float logit = d1 + blv;
                out[node1]     = 1.f / (1.f + expf(-logit));
                out[N + node1] = logit;
            }
        }
    }
}

// ---------------- host launcher ----------------
extern "C" void kernel_launch(void* const* d_in, const int* in_sizes, int n_in,
                              void* d_out, int out_size) {
    const float* x      = (const float*)d_in[0];
    const int*   eidx   = (const int*)d_in[1];
    const float* W_enc  = (const float*)d_in[2];
    const float* b_enc  = (const float*)d_in[3];
    const float* t1     = (const float*)d_in[4];
    const float* W1a    = (const float*)d_in[5];
    const float* b1a    = (const float*)d_in[6];
    const float* g1a    = (const float*)d_in[7];
    const float* be1a   = (const float*)d_in[8];
    const float* W1b    = (const float*)d_in[9];
    const float* b1b    = (const float*)d_in[10];
    const float* g_n1   = (const float*)d_in[11];
    const float* b_n1   = (const float*)d_in[12];
    const float* t2     = (const float*)d_in[13];
    const float* W2a    = (const float*)d_in[14];
    const float* b2a    = (const float*)d_in[15];
    const float* g2a    = (const float*)d_in[16];
    const float* be2a   = (const float*)d_in[17];
    const float* W2b    = (const float*)d_in[18];
    const float* b2b    = (const float*)d_in[19];
    const float* g_n0   = (const float*)d_in[20];
    const float* b_n0   = (const float*)d_in[21];
    const float* W_lin  = (const float*)d_in[22];
    const float* b_lin  = (const float*)d_in[23];
    float* out = (float*)d_out;

    int N = in_sizes[0] / 16;
    int E = in_sizes[1] / 2;
    if (N > MAXN) N = MAXN;
    if (E > MAXE) E = MAXE;
    const int* src = eidx;
    const int* dst = eidx + E;

    float *pA, *pB, *pC, *pE;
    uint4* pP;
    __half *pH, *T1a, *T1b, *T2a, *T2b;
    int *pCnt, *pAdj;
    cudaGetSymbolAddress((void**)&pA, d_bufA);
    cudaGetSymbolAddress((void**)&pB, d_bufB);
    cudaGetSymbolAddress((void**)&pC, d_bufC);
    cudaGetSymbolAddress((void**)&pE, d_bufE);
    cudaGetSymbolAddress((void**)&pP, d_P);
    cudaGetSymbolAddress((void**)&pH, d_hidG);
    cudaGetSymbolAddress((void**)&pCnt, d_cnt);
    cudaGetSymbolAddress((void**)&pAdj, d_adj);
    cudaGetSymbolAddress((void**)&T1a, d_W1aT);
    cudaGetSymbolAddress((void**)&T1b, d_W1bT);
    cudaGetSymbolAddress((void**)&T2a, d_W2aT);
    cudaGetSymbolAddress((void**)&T2b, d_W2bT);

    cudaFuncSetAttribute(k_mlpA, cudaFuncAttributeMaxDynamicSharedMemorySize, MA_TOT);
    cudaFuncSetAttribute(k_mlpB<0>, cudaFuncAttributeMaxDynamicSharedMemorySize, MB_TOT);
    cudaFuncSetAttribute(k_mlpB<1>, cudaFuncAttributeMaxDynamicSharedMemorySize, MB_TOT);

    int mlp_grid = (N + 127) / 128;
    int agg_grid = (N * 16 + 255) / 256;

    // (1) encoder -> h0 + layer-1 P + zero cnt + fp16 weight transpose
    k_encoder<<<(N * 16 + 255) / 256, 256>>>(x, W_enc, b_enc, pE, pP, t1, pCnt, N,
                                             W1a, W1b, W2a, W2b,
                                             T1a, T1b, T2a, T2b);
    // (2) bucket placement
    k_place<<<(E + 255) / 256, 256>>>(src, dst, pCnt, pAdj, E);
    // (3) layer-1 aggregation
    k_agg<<<agg_grid, 256>>>((const float4*)pE, (float4*)pA, pP, pCnt, pAdj, N);
    // (4) MLP1-A (HMMA)   [profiled slot]
    k_mlpA<<<mlp_grid, 256, MA_TOT>>>(pA, pH, T1a, b1a, g1a, be1a, N);
    // (5) MLP1-B (HMMA) -> h1 (bufB), relu(LN(h1)) (bufC), layer-2 P
    k_mlpB<0><<<mlp_grid, 256, MB_TOT>>>(pH, pB, pC, (const float*)0,
                                         T1b, b1b, g_n1, b_n1,
                                         (const float*)0, (const float*)0, pP, t2, N);
    // (6) layer-2 aggregation
    k_agg<<<agg_grid, 256>>>((const float4*)pC, (float4*)pA, pP, pCnt, pAdj, N);
    // (7) MLP2-A (HMMA)
    k_mlpA<<<mlp_grid, 256, MA_TOT>>>(pA, pH, T2a, b2a, g2a, be2a, N);
    // (8) MLP2-B (HMMA) + residual + final head -> out
    k_mlpB<1><<<mlp_grid, 256, MB_TOT>>>(pH, out, (float*)0, pB,
                                         T2b, b2b, g_n0, b_n0,
                                         W_lin, b_lin, (uint4*)0, (const float*)0, N);
}

// round 16
// speedup vs baseline: 1.7590x; 1.1962x over previous
#include <cuda_runtime.h>
#include <cuda_fp16.h>
#include <cstdint>
#include <math.h>

#define MAXN 100000
#define MAXE 1600000
#define PAD 64
#define LOG2E 1.44269504088896f

typedef unsigned long long ull;

// ---------------- scratch (static device globals; no allocs) ----------------
__device__ float  d_bufA[MAXN * 64];     // agg output (both layers)
__device__ float  d_bufB[MAXN * 64];     // h1
__device__ float  d_bufC[MAXN * 64];     // relu(LN(h1))
__device__ float  d_bufE[MAXN * 64];     // h0
__device__ uint4  d_P[MAXN * 16];        // per-node (vw,w) half2 pairs
__device__ int    d_cnt[MAXN];
__device__ int    d_adj[MAXN * PAD];
// fp16 transposed weights [j][k]
__device__ __half d_W1aT[8192], d_W1bT[8192], d_W2aT[8192], d_W2bT[8192];

// ---------------- mma.sync m16n8k16 (HMMA fallback path) --------------------
__device__ __forceinline__ void mma16816(float& c0, float& c1, float& c2, float& c3,
                                         uint32_t a0, uint32_t a1, uint32_t a2,
                                         uint32_t a3, uint32_t b0, uint32_t b1) {
    asm volatile("mma.sync.aligned.m16n8k16.row.col.f32.f16.f16.f32 "
                 "{%0,%1,%2,%3}, {%4,%5,%6,%7}, {%8,%9}, {%0,%1,%2,%3};"
                 : "+f"(c0), "+f"(c1), "+f"(c2), "+f"(c3)
                 : "r"(a0), "r"(a1), "r"(a2), "r"(a3), "r"(b0), "r"(b1));
}

// ---------------- encoder: h0 + P(t1) + zero cnt + fp16 weight transpose ----
__global__ void k_encoder(const float* __restrict__ x, const float* __restrict__ W,
                          const float* __restrict__ b, float* __restrict__ h,
                          uint4* __restrict__ P, const float* __restrict__ tptr,
                          int* __restrict__ cnt, int N,
                          const float* __restrict__ Wa1, const float* __restrict__ Wb1,
                          const float* __restrict__ Wa2, const float* __restrict__ Wb2,
                          __half* __restrict__ T1a, __half* __restrict__ T1b,
                          __half* __restrict__ T2a, __half* __restrict__ T2b) {
    __shared__ float4 sW[16 * 16];
    __shared__ float4 sB[16];
    int tid = threadIdx.x;
    if (tid < 256) sW[tid] = ((const float4*)W)[tid];
    if (tid < 16)  sB[tid] = ((const float4*)b)[tid];
    __syncthreads();
    int idx = blockIdx.x * blockDim.x + threadIdx.x;
    if (idx < N) cnt[idx] = 0;

    if (idx < 8192) {            // GEMM1 weights [64 k][128 j] -> T[j][k]
        int j = idx >> 6, k = idx & 63;
        T1a[j * 64 + k] = __float2half_rn(Wa1[k * 128 + j]);
        T2a[j * 64 + k] = __float2half_rn(Wa2[k * 128 + j]);
    } else if (idx < 16384) {    // GEMM2 weights [128 k][64 j] -> T[j][k]
        int i = idx - 8192;
        int j = i >> 7, k = i & 127;
        T1b[j * 128 + k] = __float2half_rn(Wb1[k * 64 + j]);
        T2b[j * 128 + k] = __float2half_rn(Wb2[k * 64 + j]);
    }

    int total = N * 16;
    if (idx >= total) return;
    int n = idx >> 4, q = idx & 15;
    const float4* xr = (const float4*)(x + n * 16);
    float4 x0 = xr[0], x1 = xr[1], x2 = xr[2], x3 = xr[3];
    float4 acc = sB[q];
    #define ESTEP(xv, kk) { float4 w = sW[(kk) * 16 + q]; \
        acc.x += (xv) * w.x; acc.y += (xv) * w.y; acc.z += (xv) * w.z; acc.w += (xv) * w.w; }
    ESTEP(x0.x, 0)  ESTEP(x0.y, 1)  ESTEP(x0.z, 2)  ESTEP(x0.w, 3)
    ESTEP(x1.x, 4)  ESTEP(x1.y, 5)  ESTEP(x1.z, 6)  ESTEP(x1.w, 7)
    ESTEP(x2.x, 8)  ESTEP(x2.y, 9)  ESTEP(x2.z, 10) ESTEP(x2.w, 11)
    ESTEP(x3.x, 12) ESTEP(x3.y, 13) ESTEP(x3.z, 14) ESTEP(x3.w, 15)
    #undef ESTEP
    ((float4*)h)[idx] = acc;
    float c = __ldg(tptr) * LOG2E;
    float vx = fmaxf(acc.x, 0.f) + 1e-7f;
    float vy = fmaxf(acc.y, 0.f) + 1e-7f;
    float vz = fmaxf(acc.z, 0.f) + 1e-7f;
    float vw = fmaxf(acc.w, 0.f) + 1e-7f;
    float wx = exp2f(vx * c), wy = exp2f(vy * c);
    float wz = exp2f(vz * c), ww = exp2f(vw * c);
    __half2 p0 = __floats2half2_rn(vx * wx, wx);
    __half2 p1 = __floats2half2_rn(vy * wy, wy);
    __half2 p2 = __floats2half2_rn(vz * wz, wz);
    __half2 p3 = __floats2half2_rn(vw * ww, ww);
    uint4 u;
    u.x = *(unsigned*)&p0; u.y = *(unsigned*)&p1;
    u.z = *(unsigned*)&p2; u.w = *(unsigned*)&p3;
    P[idx] = u;
}

// ---------------- bucket placement ----------------
__global__ void k_place(const int* __restrict__ src, const int* __restrict__ dst,
                        int* __restrict__ cnt, int* __restrict__ adj, int E) {
    int e = blockIdx.x * blockDim.x + threadIdx.x;
    if (e >= E) return;
    int d = dst[e];
    int p = atomicAdd(&cnt[d], 1);
    if (p < PAD) adj[(d << 6) + p] = src[e];
}

// ---------------- aggregation: fp16 P gather (round-6 best) ----------------
#define ACCP(p) { \
    float2 q0 = __half22float2(*(__half2*)&(p).x); \
    float2 q1 = __half22float2(*(__half2*)&(p).y); \
    float2 q2 = __half22float2(*(__half2*)&(p).z); \
    float2 q3 = __half22float2(*(__half2*)&(p).w); \
    n0 += q0.x; d0 += q0.y; n1 += q1.x; d1 += q1.y; \
    n2 += q2.x; d2 += q2.y; n3 += q3.x; d3 += q3.y; }

__global__ void __launch_bounds__(256)
k_agg(const float4* __restrict__ feat4, float4* __restrict__ out4,
      const uint4* __restrict__ P, const int* __restrict__ cnt,
      const int* __restrict__ adj, int N) {
    int gid = (blockIdx.x * 256 + threadIdx.x) >> 4;
    if (gid >= N) return;
    int f = threadIdx.x & 15;
    int deg = cnt[gid]; deg = min(deg, PAD);
    const int4* lst4 = (const int4*)(adj + (gid << 6));
    float n0 = 0.f, n1 = 0.f, n2 = 0.f, n3 = 0.f;
    float d0 = 0.f, d1 = 0.f, d2 = 0.f, d3 = 0.f;
    int full = deg >> 2;
    for (int c = 0; c < full; c++) {
        int4 s = lst4[c];
        uint4 p0 = P[s.x * 16 + f];
        uint4 p1 = P[s.y * 16 + f];
        uint4 p2 = P[s.z * 16 + f];
        uint4 p3 = P[s.w * 16 + f];
        ACCP(p0); ACCP(p1); ACCP(p2); ACCP(p3);
    }
    int r = deg & 3;
    if (r) {
        int4 s = lst4[full];
        uint4 p0 = P[s.x * 16 + f]; ACCP(p0);
        if (r > 1) { uint4 p1 = P[s.y * 16 + f]; ACCP(p1); }
        if (r > 2) { uint4 p2 = P[s.z * 16 + f]; ACCP(p2); }
    }
    float4 self = feat4[gid * 16 + f];
    float4 o;
    o.x = n0 / (d0 + 1e-16f) + self.x;
    o.y = n1 / (d1 + 1e-16f) + self.y;
    o.z = n2 / (d2 + 1e-16f) + self.z;
    o.w = n3 / (d3 + 1e-16f) + self.w;
    out4[gid * 16 + f] = o;
}

// ---------------- fused HMMA MLP: GEMM1 + LN128 + ReLU + GEMM2 + epilogue ---
// smem halves: sW2 @0 [64][136]=8704 | sIN @8704 [128][72]=9216 | sW1 @17920 [128][72]
// hid overwrites sIN/sW1 region: @8704 [128][136]=17408 (fits in 18432)
#define M_W2H  0
#define M_INH  8704
#define M_W1H  17920
#define M_HIDH 8704
#define M_PARB 54272
#define M_TOT  (M_PARB + 640 * 4)

template <int MODE>
__global__ void __launch_bounds__(256)
k_mlp(const float* __restrict__ in, float* __restrict__ out,
      float* __restrict__ out2, const float* __restrict__ res,
      const __half* __restrict__ W1T, const float* __restrict__ b1,
      const float* __restrict__ g1, const float* __restrict__ be1,
      const __half* __restrict__ W2T, const float* __restrict__ b2,
      const float* __restrict__ gx, const float* __restrict__ bx,
      const float* __restrict__ Wl, const float* __restrict__ bl,
      uint4* __restrict__ Pout, const float* __restrict__ tp, int N) {
    extern __shared__ char smc[];
    __half* smh = (__half*)smc;
    float* pb1 = (float*)(smc + M_PARB);
    float* pg1 = pb1 + 128;
    float* pe1 = pg1 + 128;
    float* pb2 = pe1 + 128;
    float* pgx = pb2 + 64;
    float* pbx = pgx + 64;
    float* pwl = pbx + 64;
    const int tid = threadIdx.x;

    // ---- phase 1 loads ----
    {
        int row = tid >> 1, seg = tid & 1;
        int n = blockIdx.x * 128 + row;
        int nc = (n < N) ? n : (N - 1);
        const float4* ip = (const float4*)(in + (size_t)nc * 64);
        #pragma unroll
        for (int i = 0; i < 8; i++) {
            float4 v = ip[seg * 8 + i];
            __half2 ha = __floats2half2_rn(v.x, v.y);
            __half2 hb = __floats2half2_rn(v.z, v.w);
            uint2 u;
            u.x = *(unsigned*)&ha; u.y = *(unsigned*)&hb;
            *(uint2*)(smh + M_INH + row * 72 + seg * 32 + i * 4) = u;
        }
        const uint4* w1g = (const uint4*)W1T;       // [128][64] halves
        #pragma unroll
        for (int i = 0; i < 4; i++)
            *(uint4*)(smh + M_W1H + row * 72 + seg * 32 + i * 8) =
                w1g[row * 8 + seg * 4 + i];
        int r3 = tid >> 2, s3 = tid & 3;            // W2T [64][128]
        const uint4* w2g = (const uint4*)W2T;
        #pragma unroll
        for (int i = 0; i < 4; i++)
            *(uint4*)(smh + M_W2H + r3 * 136 + s3 * 32 + i * 8) =
                w2g[r3 * 16 + s3 * 4 + i];
        if (tid < 128) { pb1[tid] = b1[tid]; pg1[tid] = g1[tid]; pe1[tid] = be1[tid]; }
        else {
            int t2 = tid - 128;
            if (t2 < 64) {
                pb2[t2] = b2[t2]; pgx[t2] = gx[t2]; pbx[t2] = bx[t2];
                pwl[t2] = (MODE == 1) ? Wl[t2] : 0.f;
            }
        }
    }
    __syncthreads();

    const int lane = tid & 31, w = tid >> 5;
    const int gid = lane >> 2, tig = lane & 3;
    const int m0 = w * 16;

    // ---- GEMM1: [128 x 128 x 64] ----
    float acc[64];
    #pragma unroll
    for (int i = 0; i < 64; i++) acc[i] = 0.f;
    {
        const __half* Ab = smh + M_INH + (m0 + gid) * 72 + tig * 2;
        #pragma unroll
        for (int ks = 0; ks < 4; ks++) {
            int k0 = ks * 16;
            uint32_t a0 = *(const uint32_t*)(Ab + k0);
            uint32_t a1 = *(const uint32_t*)(Ab + 8 * 72 + k0);
            uint32_t a2 = *(const uint32_t*)(Ab + k0 + 8);
            uint32_t a3 = *(const uint32_t*)(Ab + 8 * 72 + k0 + 8);
            #pragma unroll
            for (int nt = 0; nt < 16; nt++) {
                const __half* Bb = smh + M_W1H + (nt * 8 + gid) * 72 + tig * 2 + k0;
                uint32_t b0 = *(const uint32_t*)(Bb);
                uint32_t b1r = *(const uint32_t*)(Bb + 8);
                mma16816(acc[nt*4+0], acc[nt*4+1], acc[nt*4+2], acc[nt*4+3],
                         a0, a1, a2, a3, b0, b1r);
            }
        }
    }

    // ---- bias + LN128 stats ----
    float s0 = 0.f, q0 = 0.f, s1 = 0.f, q1 = 0.f;
    #pragma unroll
    for (int nt = 0; nt < 16; nt++) {
        int j0 = nt * 8 + tig * 2;
        float2 bb = *(float2*)&pb1[j0];
        float v0 = acc[nt*4+0] + bb.x, v1 = acc[nt*4+1] + bb.y;
        float v2 = acc[nt*4+2] + bb.x, v3 = acc[nt*4+3] + bb.y;
        acc[nt*4+0] = v0; acc[nt*4+1] = v1; acc[nt*4+2] = v2; acc[nt*4+3] = v3;
        s0 += v0 + v1; q0 += v0*v0 + v1*v1;
        s1 += v2 + v3; q1 += v2*v2 + v3*v3;
    }
    s0 += __shfl_xor_sync(0xffffffffu, s0, 1); s0 += __shfl_xor_sync(0xffffffffu, s0, 2);
    q0 += __shfl_xor_sync(0xffffffffu, q0, 1); q0 += __shfl_xor_sync(0xffffffffu, q0, 2);
    s1 += __shfl_xor_sync(0xffffffffu, s1, 1); s1 += __shfl_xor_sync(0xffffffffu, s1, 2);
    q1 += __shfl_xor_sync(0xffffffffu, q1, 1); q1 += __shfl_xor_sync(0xffffffffu, q1, 2);
    float mu0 = s0 * (1.f / 128.f), iv0 = rsqrtf(q0 * (1.f / 128.f) - mu0 * mu0 + 1e-5f);
    float mu1 = s1 * (1.f / 128.f), iv1 = rsqrtf(q1 * (1.f / 128.f) - mu1 * mu1 + 1e-5f);

    // wait for ALL warps to finish reading sIN/sW1 before overwriting with hid
    __syncthreads();

    // ---- LN + ReLU -> fp16 hid [128][136] (own rows only) ----
    #pragma unroll
    for (int nt = 0; nt < 16; nt++) {
        int j0 = nt * 8 + tig * 2;
        float2 gg = *(float2*)&pg1[j0];
        float2 ee = *(float2*)&pe1[j0];
        float y00 = fmaxf((acc[nt*4+0] - mu0) * iv0 * gg.x + ee.x, 0.f);
        float y01 = fmaxf((acc[nt*4+1] - mu0) * iv0 * gg.y + ee.y, 0.f);
        float y10 = fmaxf((acc[nt*4+2] - mu1) * iv1 * gg.x + ee.x, 0.f);
        float y11 = fmaxf((acc[nt*4+3] - mu1) * iv1 * gg.y + ee.y, 0.f);
        __half2 h0 = __floats2half2_rn(y00, y01);
        __half2 h1v = __floats2half2_rn(y10, y11);
        *(uint32_t*)(smh + M_HIDH + (m0 + gid) * 136 + j0)     = *(unsigned*)&h0;
        *(uint32_t*)(smh + M_HIDH + (m0 + gid + 8) * 136 + j0) = *(unsigned*)&h1v;
    }
    __syncwarp();

    // ---- GEMM2: [128 x 64 x 128] (A = own hid rows; no block sync needed) --
    float acc2[32];
    #pragma unroll
    for (int i = 0; i < 32; i++) acc2[i] = 0.f;
    {
        const __half* Ab = smh + M_HIDH + (m0 + gid) * 136 + tig * 2;
        #pragma unroll
        for (int ks = 0; ks < 8; ks++) {
            int k0 = ks * 16;
            uint32_t a0 = *(const uint32_t*)(Ab + k0);
            uint32_t a1 = *(const uint32_t*)(Ab + 8 * 136 + k0);
            uint32_t a2 = *(const uint32_t*)(Ab + k0 + 8);
            uint32_t a3 = *(const uint32_t*)(Ab + 8 * 136 + k0 + 8);
            #pragma unroll
            for (int nt = 0; nt < 8; nt++) {
                const __half* Bb = smh + M_W2H + (nt * 8 + gid) * 136 + tig * 2 + k0;
                uint32_t b0 = *(const uint32_t*)(Bb);
                uint32_t b1r = *(const uint32_t*)(Bb + 8);
                mma16816(acc2[nt*4+0], acc2[nt*4+1], acc2[nt*4+2], acc2[nt*4+3],
                         a0, a1, a2, a3, b0, b1r);
            }
        }
    }

    const int node0 = blockIdx.x * 128 + m0 + gid;
    const int node1 = node0 + 8;
    const int nc0 = (node0 < N) ? node0 : (N - 1);
    const int nc1 = (node1 < N) ? node1 : (N - 1);

    // ---- bias (+res), h1 store (MODE 0), LN64 stats ----
    float sa = 0.f, qa = 0.f, sb = 0.f, qb = 0.f;
    #pragma unroll
    for (int nt = 0; nt < 8; nt++) {
        int j0 = nt * 8 + tig * 2;
        float2 bb = *(float2*)&pb2[j0];
        float v0 = acc2[nt*4+0] + bb.x, v1 = acc2[nt*4+1] + bb.y;
        float v2 = acc2[nt*4+2] + bb.x, v3 = acc2[nt*4+3] + bb.y;
        if (MODE == 1) {
            float2 r0 = *(const float2*)(res + (size_t)nc0 * 64 + j0);
            float2 r1 = *(const float2*)(res + (size_t)nc1 * 64 + j0);
            v0 += r0.x; v1 += r0.y; v2 += r1.x; v3 += r1.y;
        } else {
            if (node0 < N) *(float2*)(out + (size_t)node0 * 64 + j0) = make_float2(v0, v1);
            if (node1 < N) *(float2*)(out + (size_t)node1 * 64 + j0) = make_float2(v2, v3);
        }
        acc2[nt*4+0] = v0; acc2[nt*4+1] = v1; acc2[nt*4+2] = v2; acc2[nt*4+3] = v3;
        sa += v0 + v1; qa += v0*v0 + v1*v1;
        sb += v2 + v3; qb += v2*v2 + v3*v3;
    }
    sa += __shfl_xor_sync(0xffffffffu, sa, 1); sa += __shfl_xor_sync(0xffffffffu, sa, 2);
    qa += __shfl_xor_sync(0xffffffffu, qa, 1); qa += __shfl_xor_sync(0xffffffffu, qa, 2);
    sb += __shfl_xor_sync(0xffffffffu, sb, 1); sb += __shfl_xor_sync(0xffffffffu, sb, 2);
    qb += __shfl_xor_sync(0xffffffffu, qb, 1); qb += __shfl_xor_sync(0xffffffffu, qb, 2);
    float mu0b = sa * (1.f / 64.f), iv0b = rsqrtf(qa * (1.f / 64.f) - mu0b * mu0b + 1e-5f);
    float mu1b = sb * (1.f / 64.f), iv1b = rsqrtf(qb * (1.f / 64.f) - mu1b * mu1b + 1e-5f);

    if (MODE == 0) {
        float cP = __ldg(tp) * LOG2E;
        unsigned* P32 = (unsigned*)Pout;
        #pragma unroll
        for (int nt = 0; nt < 8; nt++) {
            int j0 = nt * 8 + tig * 2;
            float2 gg = *(float2*)&pgx[j0];
            float2 ee = *(float2*)&pbx[j0];
            float y00 = fmaxf((acc2[nt*4+0] - mu0b) * iv0b * gg.x + ee.x, 0.f);
            float y01 = fmaxf((acc2[nt*4+1] - mu0b) * iv0b * gg.y + ee.y, 0.f);
            float y10 = fmaxf((acc2[nt*4+2] - mu1b) * iv1b * gg.x + ee.x, 0.f);
            float y11 = fmaxf((acc2[nt*4+3] - mu1b) * iv1b * gg.y + ee.y, 0.f);
            if (node0 < N) {
                *(float2*)(out2 + (size_t)node0 * 64 + j0) = make_float2(y00, y01);
                float va = y00 + 1e-7f, vb = y01 + 1e-7f;
                float wa = exp2f(va * cP), wb = exp2f(vb * cP);
                __half2 pa = __floats2half2_rn(va * wa, wa);
                __half2 pbh = __floats2half2_rn(vb * wb, wb);
                P32[(size_t)node0 * 64 + j0]     = *(unsigned*)&pa;
                P32[(size_t)node0 * 64 + j0 + 1] = *(unsigned*)&pbh;
            }
            if (node1 < N) {
                *(float2*)(out2 + (size_t)node1 * 64 + j0) = make_float2(y10, y11);
                float va = y10 + 1e-7f, vb = y11 + 1e-7f;
                float wa = exp2f(va * cP), wb = exp2f(vb * cP);
                __half2 pa = __floats2half2_rn(va * wa, wa);
                __half2 pbh = __floats2half2_rn(vb * wb, wb);
                P32[(size_t)node1 * 64 + j0]     = *(unsigned*)&pa;
                P32[(size_t)node1 * 64 + j0 + 1] = *(unsigned*)&pbh;
            }
        }
    } else {
        float dd0 = 0.f, dd1 = 0.f;
        #pragma unroll
        for (int nt = 0; nt < 8; nt++) {
            int j0 = nt * 8 + tig * 2;
            float2 gg = *(float2*)&pgx[j0];
            float2 ee = *(float2*)&pbx[j0];
            float2 wl = *(float2*)&pwl[j0];
            float y00 = fmaxf((acc2[nt*4+0] - mu0b) * iv0b * gg.x + ee.x, 0.f);
            float y01 = fmaxf((acc2[nt*4+1] - mu0b) * iv0b * gg.y + ee.y, 0.f);
            float y10 = fmaxf((acc2[nt*4+2] - mu1b) * iv1b * gg.x + ee.x, 0.f);
            float y11 = fmaxf((acc2[nt*4+3] - mu1b) * iv1b * gg.y + ee.y, 0.f);
            dd0 += y00 * wl.x + y01 * wl.y;
            dd1 += y10 * wl.x + y11 * wl.y;
        }
        dd0 += __shfl_xor_sync(0xffffffffu, dd0, 1); dd0 += __shfl_xor_sync(0xffffffffu, dd0, 2);
        dd1 += __shfl_xor_sync(0xffffffffu, dd1, 1); dd1 += __shfl_xor_sync(0xffffffffu, dd1, 2);
        if (tig == 0) {
            float blv = __ldg(bl);
            if (node0 < N) {
                float logit = dd0 + blv;
                out[node0]     = 1.f / (1.f + expf(-logit));
                out[N + node0] = logit;
            }
            if (node1 < N) {
                float logit = dd1 + blv;
                out[node1]     = 1.f / (1.f + expf(-logit));
                out[N + node1] = logit;
            }
        }
    }
}

// ---------------- host launcher ----------------
extern "C" void kernel_launch(void* const* d_in, const int* in_sizes, int n_in,
                              void* d_out, int out_size) {
    const float* x      = (const float*)d_in[0];
    const int*   eidx   = (const int*)d_in[1];
    const float* W_enc  = (const float*)d_in[2];
    const float* b_enc  = (const float*)d_in[3];
    const float* t1     = (const float*)d_in[4];
    const float* W1a    = (const float*)d_in[5];
    const float* b1a    = (const float*)d_in[6];
    const float* g1a    = (const float*)d_in[7];
    const float* be1a   = (const float*)d_in[8];
    const float* W1b    = (const float*)d_in[9];
    const float* b1b    = (const float*)d_in[10];
    const float* g_n1   = (const float*)d_in[11];
    const float* b_n1   = (const float*)d_in[12];
    const float* t2     = (const float*)d_in[13];
    const float* W2a    = (const float*)d_in[14];
    const float* b2a    = (const float*)d_in[15];
    const float* g2a    = (const float*)d_in[16];
    const float* be2a   = (const float*)d_in[17];
    const float* W2b    = (const float*)d_in[18];
    const float* b2b    = (const float*)d_in[19];
    const float* g_n0   = (const float*)d_in[20];
    const float* b_n0   = (const float*)d_in[21];
    const float* W_lin  = (const float*)d_in[22];
    const float* b_lin  = (const float*)d_in[23];
    float* out = (float*)d_out;

    int N = in_sizes[0] / 16;
    int E = in_sizes[1] / 2;
    if (N > MAXN) N = MAXN;
    if (E > MAXE) E = MAXE;
    const int* src = eidx;
    const int* dst = eidx + E;

    float *pA, *pB, *pC, *pE;
    uint4* pP;
    __half *T1a, *T1b, *T2a, *T2b;
    int *pCnt, *pAdj;
    cudaGetSymbolAddress((void**)&pA, d_bufA);
    cudaGetSymbolAddress((void**)&pB, d_bufB);
    cudaGetSymbolAddress((void**)&pC, d_bufC);
    cudaGetSymbolAddress((void**)&pE, d_bufE);
    cudaGetSymbolAddress((void**)&pP, d_P);
    cudaGetSymbolAddress((void**)&pCnt, d_cnt);
    cudaGetSymbolAddress((void**)&pAdj, d_adj);
    cudaGetSymbolAddress((void**)&T1a, d_W1aT);
    cudaGetSymbolAddress((void**)&T1b, d_W1bT);
    cudaGetSymbolAddress((void**)&T2a, d_W2aT);
    cudaGetSymbolAddress((void**)&T2b, d_W2bT);

    cudaFuncSetAttribute(k_mlp<0>, cudaFuncAttributeMaxDynamicSharedMemorySize, M_TOT);
    cudaFuncSetAttribute(k_mlp<1>, cudaFuncAttributeMaxDynamicSharedMemorySize, M_TOT);

    int mlp_grid = (N + 127) / 128;
    int agg_grid = (N * 16 + 255) / 256;

    // (1) encoder -> h0 + layer-1 P + zero cnt + fp16 weight transpose
    k_encoder<<<(N * 16 + 255) / 256, 256>>>(x, W_enc, b_enc, pE, pP, t1, pCnt, N,
                                             W1a, W1b, W2a, W2b,
                                             T1a, T1b, T2a, T2b);
    // (2) bucket placement
    k_place<<<(E + 255) / 256, 256>>>(src, dst, pCnt, pAdj, E);
    // (3) layer-1 aggregation
    k_agg<<<agg_grid, 256>>>((const float4*)pE, (float4*)pA, pP, pCnt, pAdj, N);
    // (4) fused MLP1 (HMMA) -> h1 (bufB), relu(LN(h1)) (bufC), layer-2 P [profiled]
    k_mlp<0><<<mlp_grid, 256, M_TOT>>>(pA, pB, pC, (const float*)0,
                                       T1a, b1a, g1a, be1a,
                                       T1b, b1b, g_n1, b_n1,
                                       (const float*)0, (const float*)0, pP, t2, N);
    // (5) layer-2 aggregation
    k_agg<<<agg_grid, 256>>>((const float4*)pC, (float4*)pA, pP, pCnt, pAdj, N);
    // (6) fused MLP2 (HMMA) + residual + final head -> out
    k_mlp<1><<<mlp_grid, 256, M_TOT>>>(pA, out, (float*)0, pB,
                                       T2a, b2a, g2a, be2a,
                                       T2b, b2b, g_n0, b_n0,
                                       W_lin, b_lin, (uint4*)0, (const float*)0, N);
}